// round 2
// baseline (speedup 1.0000x reference)
#include <cuda_runtime.h>

// Problem constants
#define NB    16
#define CIN   512
#define COUT  512
#define STY   512
#define Hdim  64
#define Wdim  64
#define HW    4096          // 64*64
#define KTOT  4608          // CIN*9
#define EPSV  1e-8f

// Device scratch (no cudaMalloc allowed)
__device__ float g_s[NB * CIN];          // modulation scales s[n, ci]
__device__ float g_demod[NB * COUT];     // demod[n, co]
__device__ float g_wsq[COUT * CIN];      // sum_k w^2 per (co, ci)
__device__ float g_wT[KTOT * COUT];      // weight transposed to [k][co]

// ---------------------------------------------------------------------------
// s[n, ci] = dot(style[n,:], style_w[ci,:]) + style_b[ci]
// grid = NB blocks, 512 threads (one ci per thread)
// ---------------------------------------------------------------------------
__global__ void k_style(const float* __restrict__ style,
                        const float* __restrict__ style_w,
                        const float* __restrict__ style_b) {
    int n  = blockIdx.x;
    int ci = threadIdx.x;
    const float* srow = style + n * STY;
    const float* wrow = style_w + ci * STY;
    float acc = 0.f;
    #pragma unroll 8
    for (int j = 0; j < STY; j++) acc += srow[j] * wrow[j];
    g_s[n * CIN + ci] = acc + style_b[ci];
}

// ---------------------------------------------------------------------------
// wsq[co, ci] = sum_k weight[co,ci,k]^2 ; also transpose weight to [k][co]
// grid = COUT blocks, 512 threads (one ci per thread)
// ---------------------------------------------------------------------------
__global__ void k_wsq(const float* __restrict__ weight) {
    int co = blockIdx.x;
    int ci = threadIdx.x;
    const float* wp = weight + (size_t)co * KTOT + ci * 9;
    float s = 0.f;
    #pragma unroll
    for (int t = 0; t < 9; t++) {
        float v = wp[t];
        s += v * v;
        g_wT[(ci * 9 + t) * COUT + co] = v;
    }
    g_wsq[co * CIN + ci] = s;
}

// ---------------------------------------------------------------------------
// demod[n, co] = rsqrt( sum_ci wsq[co,ci] * s[n,ci]^2 + eps )
// grid = (COUT, NB), 128 threads
// ---------------------------------------------------------------------------
__global__ void k_demod() {
    int co = blockIdx.x;
    int n  = blockIdx.y;
    __shared__ float red[128];
    float acc = 0.f;
    for (int ci = threadIdx.x; ci < CIN; ci += 128) {
        float s = g_s[n * CIN + ci];
        acc += g_wsq[co * CIN + ci] * s * s;
    }
    red[threadIdx.x] = acc;
    __syncthreads();
    for (int st = 64; st > 0; st >>= 1) {
        if (threadIdx.x < st) red[threadIdx.x] += red[threadIdx.x + st];
        __syncthreads();
    }
    if (threadIdx.x == 0) g_demod[n * COUT + co] = rsqrtf(red[0] + EPSV);
}

// ---------------------------------------------------------------------------
// Main implicit-GEMM conv:
//   GEMM view: out[m, co],  m = (n, h, w),  k = (ci, kh, kw)
//   A[k][m] = x[n, ci, h+kh-1, w+kw-1] * s[n, ci]   (im2col on the fly)
//   B[k][co] = weight[co, ci, kh, kw]               (pre-transposed g_wT)
// Tile: 128 pixels x 128 couts x K-chunk 8, 256 threads, 8x8 per thread.
// Epilogue: *demod + noise_weight*noise, LeakyReLU(0.2).
// grid = (NB*32, COUT/128), block = 256
// ---------------------------------------------------------------------------
__global__ __launch_bounds__(256, 2)
void k_conv(const float* __restrict__ x,
            const float* __restrict__ noise,
            const float* __restrict__ noise_weight,
            float* __restrict__ out) {
    int n     = blockIdx.x >> 5;          // 32 m-tiles per sample
    int mtile = blockIdx.x & 31;
    int m0    = mtile * 128;              // covers 2 full rows (h0, h0+1)
    int co0   = blockIdx.y * 128;

    __shared__ float As[8][128];
    __shared__ float Bs[8][128];

    int t  = threadIdx.x;
    int tx = t & 15;        // co direction
    int ty = t >> 4;        // pixel direction

    float acc[8][8];        // [ic][im]
    #pragma unroll
    for (int i = 0; i < 8; i++)
        #pragma unroll
        for (int j = 0; j < 8; j++) acc[i][j] = 0.f;

    const float* xn = x + (size_t)n * CIN * HW;
    const float* sn = g_s + n * CIN;

    for (int k0 = 0; k0 < KTOT; k0 += 8) {
        // ---- load A tile (im2col + modulation) ----
        #pragma unroll
        for (int i = 0; i < 4; i++) {
            int idx = t + i * 256;
            int kk = idx >> 7, mm = idx & 127;
            int k  = k0 + kk;
            int ci = k / 9;
            int r  = k - ci * 9;
            int r3 = r / 3;
            int dh = r3 - 1;
            int dw = (r - r3 * 3) - 1;
            int m  = m0 + mm;
            int h  = m >> 6, w = m & 63;
            int hi = h + dh, wi = w + dw;
            float v = 0.f;
            if ((unsigned)hi < (unsigned)Hdim && (unsigned)wi < (unsigned)Wdim)
                v = xn[ci * HW + hi * Wdim + wi] * sn[ci];
            As[kk][mm] = v;
        }
        // ---- load B tile (coalesced from transposed weights) ----
        #pragma unroll
        for (int i = 0; i < 4; i++) {
            int idx = t + i * 256;
            int kk = idx >> 7, cc = idx & 127;
            Bs[kk][cc] = g_wT[(k0 + kk) * COUT + co0 + cc];
        }
        __syncthreads();

        // ---- 8x8 outer-product accumulation ----
        #pragma unroll
        for (int kk = 0; kk < 8; kk++) {
            float a[8], b[8];
            #pragma unroll
            for (int i = 0; i < 4; i++) {
                ((float4*)a)[0] = *(const float4*)&As[kk][ty * 8];
                ((float4*)a)[1] = *(const float4*)&As[kk][ty * 8 + 4];
                ((float4*)b)[0] = *(const float4*)&Bs[kk][tx * 8];
                ((float4*)b)[1] = *(const float4*)&Bs[kk][tx * 8 + 4];
                break;  // (single vector load; loop form keeps compiler happy)
            }
            #pragma unroll
            for (int ic = 0; ic < 8; ic++)
                #pragma unroll
                for (int im = 0; im < 8; im++)
                    acc[ic][im] += b[ic] * a[im];
        }
        __syncthreads();
    }

    // ---- epilogue: demod, noise, LeakyReLU, vectorized store ----
    float nw = noise_weight[0];
    const float* np = noise + (size_t)n * HW + m0 + ty * 8;
    #pragma unroll
    for (int ic = 0; ic < 8; ic++) {
        int co = co0 + tx * 8 + ic;
        float d = g_demod[n * COUT + co];
        float* op = out + ((size_t)n * COUT + co) * HW + m0 + ty * 8;
        float tmp[8];
        #pragma unroll
        for (int im = 0; im < 8; im++) {
            float v = acc[ic][im] * d + nw * np[im];
            tmp[im] = (v >= 0.f) ? v : 0.2f * v;
        }
        ((float4*)op)[0] = make_float4(tmp[0], tmp[1], tmp[2], tmp[3]);
        ((float4*)op)[1] = make_float4(tmp[4], tmp[5], tmp[6], tmp[7]);
    }
}

// ---------------------------------------------------------------------------
extern "C" void kernel_launch(void* const* d_in, const int* in_sizes, int n_in,
                              void* d_out, int out_size) {
    const float* x            = (const float*)d_in[0];  // (16,512,64,64)
    const float* style        = (const float*)d_in[1];  // (16,512)
    const float* noise        = (const float*)d_in[2];  // (16,1,64,64)
    const float* weight       = (const float*)d_in[3];  // (1,512,512,3,3)
    const float* style_w      = (const float*)d_in[4];  // (512,512)
    const float* style_b      = (const float*)d_in[5];  // (512,)
    const float* noise_weight = (const float*)d_in[6];  // (1,)
    float* out = (float*)d_out;                         // (16,512,64,64)

    k_style<<<NB, CIN>>>(style, style_w, style_b);
    k_wsq<<<COUT, CIN>>>(weight);
    {
        dim3 g(COUT, NB);
        k_demod<<<g, 128>>>();
    }
    {
        dim3 g(NB * 32, COUT / 128);
        k_conv<<<g, 256>>>(x, noise, noise_weight, out);
    }
}

// round 4
// speedup vs baseline: 2.8066x; 2.8066x over previous
#include <cuda_runtime.h>
#include <cuda_fp16.h>
#include <cstdint>

#define NB    16
#define CIN   512
#define COUT  512
#define STY   512
#define HW    4096
#define EPSV  1e-8f

#define XM_GUARD 2048                       // half elements of guard each side
#define XM_ELEMS (NB * 32 * HW * 16)        // 33,554,432 halfs per plane

// ---------------- device scratch ----------------
__device__ float g_s[NB * CIN];
__device__ float g_demod[NB * COUT];
__device__ float g_wsq[COUT * CIN];
__device__ __half g_xmHi[XM_ELEMS + 2 * XM_GUARD];   // x*s hi, [n][c16][p][16]
__device__ __half g_xmLo[XM_ELEMS + 2 * XM_GUARD];   // x*s lo residual
__device__ __half g_wB[9 * 32 * COUT * 16];          // weights [tap][c16][co][16]

// ---------------- PTX helpers ----------------
__device__ __forceinline__ uint32_t smem_u32(const void* p) {
    uint32_t a;
    asm("{ .reg .u64 t; cvta.to.shared.u64 t, %1; cvt.u32.u64 %0, t; }" : "=r"(a) : "l"(p));
    return a;
}
#define MBAR_INIT(mb, c) asm volatile("mbarrier.init.shared.b64 [%0], %1;" :: "r"((uint32_t)(mb)), "r"((uint32_t)(c)) : "memory")
#define MBAR_ARRIVE(mb)  asm volatile("mbarrier.arrive.shared.b64 _, [%0];" :: "r"((uint32_t)(mb)) : "memory")
#define MBAR_EXPECT(mb, n) asm volatile("mbarrier.arrive.expect_tx.shared.b64 _, [%0], %1;" :: "r"((uint32_t)(mb)), "r"((uint32_t)(n)) : "memory")
#define FENCE_ASYNC()    asm volatile("fence.proxy.async.shared::cta;" ::: "memory")

#define MBAR_WAIT(mb, ph) do {                                                   \
    uint32_t _mb = (uint32_t)(mb); uint32_t _ph = (uint32_t)(ph); uint32_t _dn;  \
    asm volatile("{ .reg .pred p; mbarrier.try_wait.parity.acquire.cta.shared::cta.b64 p, [%1], %2; selp.b32 %0, 1, 0, p; }" \
        : "=r"(_dn) : "r"(_mb), "r"(_ph) : "memory");                            \
    if (!_dn) {                                                                  \
        asm volatile("{ .reg .pred P1;\n"                                        \
            "WL_%=: mbarrier.try_wait.parity.acquire.cta.shared::cta.b64 P1, [%0], %1, 0x989680;\n" \
            "@P1 bra.uni WD_%=;\n bra.uni WL_%=;\n WD_%=: }"                     \
            :: "r"(_mb), "r"(_ph) : "memory");                                   \
    }                                                                            \
} while (0)

#define BULK(dst, src, sz, mb) \
    asm volatile("cp.async.bulk.shared::cta.global.mbarrier::complete_tx::bytes [%0], [%1], %2, [%3];" \
        :: "r"((uint32_t)(dst)), "l"(src), "r"((uint32_t)(sz)), "r"((uint32_t)(mb)) : "memory")

#define LDSM4(r, a) \
    asm volatile("ldmatrix.sync.aligned.m8n8.x4.shared.b16 {%0,%1,%2,%3}, [%4];" \
        : "=r"((r)[0]), "=r"((r)[1]), "=r"((r)[2]), "=r"((r)[3]) : "r"(a))

#define LDS32(v, a) asm volatile("ld.shared.b32 %0, [%1];" : "=r"(v) : "r"(a))

__device__ __forceinline__ void mma_f16(float* c, const uint32_t* a, const uint32_t* b) {
    asm volatile("mma.sync.aligned.m16n8k16.row.col.f32.f16.f16.f32 "
        "{%0,%1,%2,%3}, {%4,%5,%6,%7}, {%8,%9}, {%0,%1,%2,%3};"
        : "+f"(c[0]), "+f"(c[1]), "+f"(c[2]), "+f"(c[3])
        : "r"(a[0]), "r"(a[1]), "r"(a[2]), "r"(a[3]), "r"(b[0]), "r"(b[1]));
}

// ---------------- prep kernels ----------------
__global__ void k_style(const float* __restrict__ style,
                        const float* __restrict__ style_w,
                        const float* __restrict__ style_b) {
    int n = blockIdx.x, ci = threadIdx.x;
    const float* srow = style + n * STY;
    const float* wrow = style_w + ci * STY;
    float acc = 0.f;
    #pragma unroll 8
    for (int j = 0; j < STY; j++) acc += srow[j] * wrow[j];
    g_s[n * CIN + ci] = acc + style_b[ci];
}

__global__ void k_wsq(const float* __restrict__ weight) {
    int co = blockIdx.x, ci = threadIdx.x;
    const float* wp = weight + (size_t)co * CIN * 9 + ci * 9;
    float s = 0.f;
    #pragma unroll
    for (int t = 0; t < 9; t++) { float v = wp[t]; s += v * v; }
    g_wsq[co * CIN + ci] = s;
}

__global__ void k_demod() {
    int co = blockIdx.x, n = blockIdx.y;
    __shared__ float red[128];
    float acc = 0.f;
    for (int ci = threadIdx.x; ci < CIN; ci += 128) {
        float s = g_s[n * CIN + ci];
        acc += g_wsq[co * CIN + ci] * s * s;
    }
    red[threadIdx.x] = acc;
    __syncthreads();
    for (int st = 64; st > 0; st >>= 1) {
        if (threadIdx.x < st) red[threadIdx.x] += red[threadIdx.x + st];
        __syncthreads();
    }
    if (threadIdx.x == 0) g_demod[n * COUT + co] = rsqrtf(red[0] + EPSV);
}

// weights -> fp16 [tap][c16][co][16ci]
__global__ void k_wprep(const float* __restrict__ weight) {
    int id = blockIdx.x * 256 + threadIdx.x;     // 262144
    int ci = id & 511, co = id >> 9;
    const float* wp = weight + (size_t)(co * CIN + ci) * 9;
    int c16 = ci >> 4, cil = ci & 15;
    #pragma unroll
    for (int tap = 0; tap < 9; tap++)
        g_wB[((size_t)(tap * 32 + c16) * COUT + co) * 16 + cil] = __float2half_rn(wp[tap]);
}

// x*s -> fp16 hi/lo planes in [n][c16][p][16ci] layout
__global__ void k_xmod(const float* __restrict__ x) {
    int b   = blockIdx.x;                        // 0..8191
    int n   = b >> 9;
    int c16 = (b >> 4) & 31;
    int pb  = b & 15;
    int p   = pb * 256 + threadIdx.x;
    const float* sp = g_s + n * CIN + c16 * 16;
    const float* xp = x + (size_t)(n * CIN + c16 * 16) * HW + p;
    uint32_t hi[8], lo[8];
    #pragma unroll
    for (int j = 0; j < 8; j++) {
        float v0 = xp[(size_t)(2 * j) * HW]     * sp[2 * j];
        float v1 = xp[(size_t)(2 * j + 1) * HW] * sp[2 * j + 1];
        __half h0 = __float2half_rn(v0), h1 = __float2half_rn(v1);
        __half l0 = __float2half_rn(v0 - __half2float(h0));
        __half l1 = __float2half_rn(v1 - __half2float(h1));
        __half2 hp = __halves2half2(h0, h1);
        __half2 lp = __halves2half2(l0, l1);
        hi[j] = *reinterpret_cast<uint32_t*>(&hp);
        lo[j] = *reinterpret_cast<uint32_t*>(&lp);
    }
    size_t ob = (size_t)XM_GUARD + ((size_t)(n * 32 + c16) * HW + p) * 16;
    uint4* oh = reinterpret_cast<uint4*>(g_xmHi + ob);
    uint4* ol = reinterpret_cast<uint4*>(g_xmLo + ob);
    oh[0] = make_uint4(hi[0], hi[1], hi[2], hi[3]);
    oh[1] = make_uint4(hi[4], hi[5], hi[6], hi[7]);
    ol[0] = make_uint4(lo[0], lo[1], lo[2], lo[3]);
    ol[1] = make_uint4(lo[4], lo[5], lo[6], lo[7]);
}

// ---------------- main HMMA kernel ----------------
#define NSTG      4
#define STG_BYTES 20480      // Ahi 8192 | Alo 8192 | B 4096
#define SM_DATA   1024
#define SMEM_TOTAL (SM_DATA + NSTG * STG_BYTES)   // 82944

__device__ __forceinline__ void issue_stage(uint32_t sb, int st, int n, int p0, int co0) {
    int c16 = st / 9;
    int tap = st - c16 * 9;
    int off = (tap / 3 - 1) * 64 + (tap % 3 - 1);
    int slot = st & 3;
    uint32_t sa = sb + SM_DATA + slot * STG_BYTES;
    uint32_t mb = sb + slot * 8;
    MBAR_EXPECT(mb, STG_BYTES);
    const __half* aH = g_xmHi + XM_GUARD + ((long)(n * 32 + c16) * HW + p0 + off) * 16;
    const __half* aL = g_xmLo + XM_GUARD + ((long)(n * 32 + c16) * HW + p0 + off) * 16;
    const __half* bS = g_wB + ((long)(tap * 32 + c16) * COUT + co0) * 16;
    BULK(sa,         aH, 8192, mb);
    BULK(sa + 8192,  aL, 8192, mb);
    BULK(sa + 16384, bS, 4096, mb);
}

__global__ void __launch_bounds__(256, 1)
k_main(const float* __restrict__ noise,
       const float* __restrict__ nw_p,
       float* __restrict__ out) {
    extern __shared__ __align__(1024) char smem[];
    uint32_t sb = smem_u32(smem);
    int t = threadIdx.x, wid = t >> 5, lane = t & 31;
    int wm = wid & 3, wn = wid >> 2;

    int bx = blockIdx.x;                // 1024 CTAs, sample-major
    int n   = bx >> 6;
    int rem = bx & 63;
    int p0  = (rem >> 2) * 256;
    int co0 = (rem & 3) * 128;

    if (t == 0) {
        #pragma unroll
        for (int s = 0; s < NSTG; s++) {
            MBAR_INIT(sb + s * 8, 1);        // full: 1 expect_tx arrival
            MBAR_INIT(sb + 32 + s * 8, 8);   // empty: 8 warps
        }
        FENCE_ASYNC();
    }
    __syncthreads();

    if (t == 0) {
        #pragma unroll
        for (int s = 0; s < NSTG; s++) issue_stage(sb, s, n, p0, co0);
    }

    float acc[4][8][4];
    #pragma unroll
    for (int a = 0; a < 4; a++)
        #pragma unroll
        for (int b = 0; b < 8; b++)
            #pragma unroll
            for (int c = 0; c < 4; c++) acc[a][b][c] = 0.f;

    for (int it = 0; it < 288; ++it) {
        int slot = it & 3, use = it >> 2;
        uint32_t sa = sb + SM_DATA + slot * STG_BYTES;

        MBAR_WAIT(sb + slot * 8, use & 1);

        // zero-fixup of invalid A rows (this warp's 64 rows; same-warp ordering)
        {
            int c16 = it / 9;
            int tap = it - c16 * 9;
            int dh = tap / 3 - 1, dw = tap % 3 - 1;
            int pl = wm * 64 + lane * 2;
            #pragma unroll
            for (int rr = 0; rr < 2; rr++) {
                int p = p0 + pl + rr;
                int h = p >> 6, w = p & 63;
                if ((unsigned)(h + dh) >= 64u || (unsigned)(w + dw) >= 64u) {
                    uint32_t ra = sa + (pl + rr) * 32;
                    asm volatile(
                        "st.shared.v4.b32 [%0], {%2,%2,%2,%2};\n\t"
                        "st.shared.v4.b32 [%0+16], {%2,%2,%2,%2};\n\t"
                        "st.shared.v4.b32 [%1], {%2,%2,%2,%2};\n\t"
                        "st.shared.v4.b32 [%1+16], {%2,%2,%2,%2};"
                        :: "r"(ra), "r"(ra + 8192), "r"(0u) : "memory");
                }
            }
        }

        // B fragments (16 LDS.32)
        uint32_t bh[8][2];
        uint32_t bbase = sa + 16384 + (wn * 64 + (lane >> 2)) * 32 + (lane & 3) * 4;
        #pragma unroll
        for (int bn = 0; bn < 8; bn++) {
            uint32_t ba = bbase + bn * 256;     // 8 co rows * 32B
            LDS32(bh[bn][0], ba);
            LDS32(bh[bn][1], ba + 16);
        }

        // A fragments + MMA, per m16 tile
        uint32_t abase = sa + (wm * 64 + (lane & 15)) * 32 + (lane >> 4) * 16;
        #pragma unroll
        for (int am = 0; am < 4; am++) {
            uint32_t la = abase + am * 512;     // 16 rows * 32B
            uint32_t ah[4], al[4];
            LDSM4(ah, la);
            LDSM4(al, la + 8192);
            #pragma unroll
            for (int bn = 0; bn < 8; bn++) {
                mma_f16(acc[am][bn], ah, bh[bn]);
                mma_f16(acc[am][bn], al, bh[bn]);
            }
        }

        // release slot, then producer refills
        if (lane == 0) MBAR_ARRIVE(sb + 32 + slot * 8);
        if (t == 0 && it + NSTG < 288) {
            MBAR_WAIT(sb + 32 + slot * 8, use & 1);
            issue_stage(sb, it + NSTG, n, p0, co0);
        }
    }

    __syncthreads();   // all stage traffic done; reuse smem for epilogue

    // ---- epilogue: demod * acc + noise, LeakyReLU, coalesced stores ----
    {
        float nw = nw_p[0];
        int q = lane & 3, rr = lane >> 2;
        int pxbase = p0 + wm * 64 + q * 16;
        float nzs[16];
        #pragma unroll
        for (int j = 0; j < 16; j++) nzs[j] = nw * noise[n * HW + pxbase + j];

        float* wsm = reinterpret_cast<float*>(smem + SM_DATA + wid * 2048); // 512 floats
        const float* dmrow = g_demod + n * COUT;

        #pragma unroll
        for (int g = 0; g < 8; g++) {
            // scatter this warp's 64x8 sub-tile into smem [co8][px64]
            #pragma unroll
            for (int am = 0; am < 4; am++) {
                int px = am * 16 + (lane >> 2);
                int col = (lane & 3) * 2;
                wsm[col * 64 + px]           = acc[am][g][0];
                wsm[(col + 1) * 64 + px]     = acc[am][g][1];
                wsm[col * 64 + px + 8]       = acc[am][g][2];
                wsm[(col + 1) * 64 + px + 8] = acc[am][g][3];
            }
            __syncwarp();
            int co = co0 + wn * 64 + g * 8 + rr;
            float d = dmrow[co];
            float* op = out + ((size_t)(n * COUT + co)) * HW + pxbase;
            const float* srp = wsm + rr * 64 + q * 16;
            #pragma unroll
            for (int j4 = 0; j4 < 4; j4++) {
                float4 v = *reinterpret_cast<const float4*>(srp + j4 * 4);
                float r0 = v.x * d + nzs[j4 * 4 + 0];
                float r1 = v.y * d + nzs[j4 * 4 + 1];
                float r2 = v.z * d + nzs[j4 * 4 + 2];
                float r3 = v.w * d + nzs[j4 * 4 + 3];
                r0 = (r0 >= 0.f) ? r0 : 0.2f * r0;
                r1 = (r1 >= 0.f) ? r1 : 0.2f * r1;
                r2 = (r2 >= 0.f) ? r2 : 0.2f * r2;
                r3 = (r3 >= 0.f) ? r3 : 0.2f * r3;
                *reinterpret_cast<float4*>(op + j4 * 4) = make_float4(r0, r1, r2, r3);
            }
            __syncwarp();
        }
    }
}

// ---------------------------------------------------------------------------
extern "C" void kernel_launch(void* const* d_in, const int* in_sizes, int n_in,
                              void* d_out, int out_size) {
    const float* x            = (const float*)d_in[0];
    const float* style        = (const float*)d_in[1];
    const float* noise        = (const float*)d_in[2];
    const float* weight       = (const float*)d_in[3];
    const float* style_w      = (const float*)d_in[4];
    const float* style_b      = (const float*)d_in[5];
    const float* noise_weight = (const float*)d_in[6];
    float* out = (float*)d_out;

    cudaFuncSetAttribute(k_main, cudaFuncAttributeMaxDynamicSharedMemorySize, SMEM_TOTAL);

    k_style<<<NB, CIN>>>(style, style_w, style_b);
    k_wsq<<<COUT, CIN>>>(weight);
    {
        dim3 g(COUT, NB);
        k_demod<<<g, 128>>>();
    }
    k_wprep<<<1024, 256>>>(weight);
    k_xmod<<<8192, 256>>>(x);
    k_main<<<1024, 256, SMEM_TOTAL>>>(noise, noise_weight, out);
}

// round 5
// speedup vs baseline: 6.2704x; 2.2341x over previous
#include <cuda_runtime.h>
#include <cuda_fp16.h>
#include <cstdint>

#define NB    16
#define CIN   512
#define COUT  512
#define STY   512
#define HW    4096
#define EPSV  1e-8f

#define XM_GUARD 2048                       // half elements of guard each side
#define XM_ELEMS (NB * 32 * HW * 16)        // 33,554,432 halfs

// ---------------- device scratch ----------------
__device__ float g_s[NB * CIN];
__device__ float g_demod[NB * COUT];
__device__ float g_wsq[COUT * CIN];
__device__ __half g_xm[XM_ELEMS + 2 * XM_GUARD];     // x*s fp16, [n][c16][p][16]
__device__ __half g_wB[9 * 32 * COUT * 16];          // weights [tap][c16][co][16]

// ---------------- PTX helpers ----------------
__device__ __forceinline__ uint32_t smem_u32(const void* p) {
    uint32_t a;
    asm("{ .reg .u64 t; cvta.to.shared.u64 t, %1; cvt.u32.u64 %0, t; }" : "=r"(a) : "l"(p));
    return a;
}
#define MBAR_INIT(mb, c) asm volatile("mbarrier.init.shared.b64 [%0], %1;" :: "r"((uint32_t)(mb)), "r"((uint32_t)(c)) : "memory")
#define MBAR_ARRIVE(mb)  asm volatile("mbarrier.arrive.shared.b64 _, [%0];" :: "r"((uint32_t)(mb)) : "memory")
#define MBAR_EXPECT(mb, n) asm volatile("mbarrier.arrive.expect_tx.shared.b64 _, [%0], %1;" :: "r"((uint32_t)(mb)), "r"((uint32_t)(n)) : "memory")
#define FENCE_ASYNC()    asm volatile("fence.proxy.async.shared::cta;" ::: "memory")

#define MBAR_WAIT(mb, ph) do {                                                   \
    uint32_t _mb = (uint32_t)(mb); uint32_t _ph = (uint32_t)(ph); uint32_t _dn;  \
    asm volatile("{ .reg .pred p; mbarrier.try_wait.parity.acquire.cta.shared::cta.b64 p, [%1], %2; selp.b32 %0, 1, 0, p; }" \
        : "=r"(_dn) : "r"(_mb), "r"(_ph) : "memory");                            \
    if (!_dn) {                                                                  \
        asm volatile("{ .reg .pred P1;\n"                                        \
            "WL_%=: mbarrier.try_wait.parity.acquire.cta.shared::cta.b64 P1, [%0], %1, 0x989680;\n" \
            "@P1 bra.uni WD_%=;\n bra.uni WL_%=;\n WD_%=: }"                     \
            :: "r"(_mb), "r"(_ph) : "memory");                                   \
    }                                                                            \
} while (0)

#define BULK(dst, src, sz, mb) \
    asm volatile("cp.async.bulk.shared::cta.global.mbarrier::complete_tx::bytes [%0], [%1], %2, [%3];" \
        :: "r"((uint32_t)(dst)), "l"(src), "r"((uint32_t)(sz)), "r"((uint32_t)(mb)) : "memory")

#define LDSM4(r, a) \
    asm volatile("ldmatrix.sync.aligned.m8n8.x4.shared.b16 {%0,%1,%2,%3}, [%4];" \
        : "=r"((r)[0]), "=r"((r)[1]), "=r"((r)[2]), "=r"((r)[3]) : "r"(a))

__device__ __forceinline__ void mma_f16(float* c, const uint32_t* a, const uint32_t* b) {
    asm volatile("mma.sync.aligned.m16n8k16.row.col.f32.f16.f16.f32 "
        "{%0,%1,%2,%3}, {%4,%5,%6,%7}, {%8,%9}, {%0,%1,%2,%3};"
        : "+f"(c[0]), "+f"(c[1]), "+f"(c[2]), "+f"(c[3])
        : "r"(a[0]), "r"(a[1]), "r"(a[2]), "r"(a[3]), "r"(b[0]), "r"(b[1]));
}

// ---------------- prep kernels ----------------
__global__ void k_style(const float* __restrict__ style,
                        const float* __restrict__ style_w,
                        const float* __restrict__ style_b) {
    int n = blockIdx.x, ci = threadIdx.x;
    const float* srow = style + n * STY;
    const float* wrow = style_w + ci * STY;
    float acc = 0.f;
    #pragma unroll 8
    for (int j = 0; j < STY; j++) acc += srow[j] * wrow[j];
    g_s[n * CIN + ci] = acc + style_b[ci];
}

__global__ void k_wsq(const float* __restrict__ weight) {
    int co = blockIdx.x, ci = threadIdx.x;
    const float* wp = weight + (size_t)co * CIN * 9 + ci * 9;
    float s = 0.f;
    #pragma unroll
    for (int t = 0; t < 9; t++) { float v = wp[t]; s += v * v; }
    g_wsq[co * CIN + ci] = s;
}

__global__ void k_demod() {
    int co = blockIdx.x, n = blockIdx.y;
    __shared__ float red[128];
    float acc = 0.f;
    for (int ci = threadIdx.x; ci < CIN; ci += 128) {
        float s = g_s[n * CIN + ci];
        acc += g_wsq[co * CIN + ci] * s * s;
    }
    red[threadIdx.x] = acc;
    __syncthreads();
    for (int st = 64; st > 0; st >>= 1) {
        if (threadIdx.x < st) red[threadIdx.x] += red[threadIdx.x + st];
        __syncthreads();
    }
    if (threadIdx.x == 0) g_demod[n * COUT + co] = rsqrtf(red[0] + EPSV);
}

// weights -> fp16 [tap][c16][co][16ci]
__global__ void k_wprep(const float* __restrict__ weight) {
    int id = blockIdx.x * 256 + threadIdx.x;     // 262144
    int ci = id & 511, co = id >> 9;
    const float* wp = weight + (size_t)(co * CIN + ci) * 9;
    int c16 = ci >> 4, cil = ci & 15;
    #pragma unroll
    for (int tap = 0; tap < 9; tap++)
        g_wB[((size_t)(tap * 32 + c16) * COUT + co) * 16 + cil] = __float2half_rn(wp[tap]);
}

// x*s -> fp16 in [n][c16][p][16ci] layout
__global__ void k_xmod(const float* __restrict__ x) {
    int b   = blockIdx.x;                        // 0..8191
    int n   = b >> 9;
    int c16 = (b >> 4) & 31;
    int pb  = b & 15;
    int p   = pb * 256 + threadIdx.x;
    const float* sp = g_s + n * CIN + c16 * 16;
    const float* xp = x + (size_t)(n * CIN + c16 * 16) * HW + p;
    uint32_t hi[8];
    #pragma unroll
    for (int j = 0; j < 8; j++) {
        float v0 = xp[(size_t)(2 * j) * HW]     * sp[2 * j];
        float v1 = xp[(size_t)(2 * j + 1) * HW] * sp[2 * j + 1];
        __half2 hp = __halves2half2(__float2half_rn(v0), __float2half_rn(v1));
        hi[j] = *reinterpret_cast<uint32_t*>(&hp);
    }
    size_t ob = (size_t)XM_GUARD + ((size_t)(n * 32 + c16) * HW + p) * 16;
    uint4* oh = reinterpret_cast<uint4*>(g_xm + ob);
    oh[0] = make_uint4(hi[0], hi[1], hi[2], hi[3]);
    oh[1] = make_uint4(hi[4], hi[5], hi[6], hi[7]);
}

// ---------------- main HMMA kernel ----------------
#define NSTG      6
#define STG_BYTES 12288      // A 8192 | B 4096
#define SM_DATA   1024
#define SMEM_TOTAL (SM_DATA + NSTG * STG_BYTES)   // 74752

__device__ __forceinline__ void issue_stage(uint32_t sb, int st, int n, int p0, int co0) {
    int c16 = st / 9;
    int tap = st - c16 * 9;
    int off = (tap / 3 - 1) * 64 + (tap % 3 - 1);
    int slot = st % NSTG;
    uint32_t sa = sb + SM_DATA + slot * STG_BYTES;
    uint32_t mb = sb + slot * 8;
    MBAR_EXPECT(mb, STG_BYTES);
    const __half* aS = g_xm + XM_GUARD + ((long)(n * 32 + c16) * HW + p0 + off) * 16;
    const __half* bS = g_wB + ((long)(tap * 32 + c16) * COUT + co0) * 16;
    BULK(sa,        aS, 8192, mb);
    BULK(sa + 8192, bS, 4096, mb);
}

__global__ void __launch_bounds__(256, 1)
k_main(const float* __restrict__ noise,
       const float* __restrict__ nw_p,
       float* __restrict__ out) {
    extern __shared__ __align__(1024) char smem[];
    uint32_t sb = smem_u32(smem);
    int t = threadIdx.x, wid = t >> 5, lane = t & 31;
    int wm = wid & 3, wn = wid >> 2;

    int bx = blockIdx.x;                // 1024 CTAs, sample-major
    int n   = bx >> 6;
    int rem = bx & 63;
    int p0  = (rem >> 2) * 256;
    int co0 = (rem & 3) * 128;

    if (t == 0) {
        #pragma unroll
        for (int s = 0; s < NSTG; s++) {
            MBAR_INIT(sb + s * 8, 1);        // full: 1 expect_tx arrival
            MBAR_INIT(sb + 64 + s * 8, 8);   // empty: 8 warps
        }
        FENCE_ASYNC();
    }
    __syncthreads();

    if (t == 0) {
        #pragma unroll
        for (int s = 0; s < NSTG; s++) issue_stage(sb, s, n, p0, co0);
    }

    float acc[4][8][4];
    #pragma unroll
    for (int a = 0; a < 4; a++)
        #pragma unroll
        for (int b = 0; b < 8; b++)
            #pragma unroll
            for (int c = 0; c < 4; c++) acc[a][b][c] = 0.f;

    // per-lane invariant addressing pieces
    int bg = lane >> 3, br = lane & 7;     // ldmatrix B: matrix id / row

    for (int it = 0; it < 288; ++it) {
        int slot = it % NSTG, use = it / NSTG;
        uint32_t sa = sb + SM_DATA + slot * STG_BYTES;

        MBAR_WAIT(sb + slot * 8, use & 1);

        // zero-fixup of invalid A rows (this warp's 64 rows)
        {
            int c16 = it / 9;
            int tap = it - c16 * 9;
            int dh = tap / 3 - 1, dw = tap % 3 - 1;
            int pl = wm * 64 + lane * 2;
            #pragma unroll
            for (int rr = 0; rr < 2; rr++) {
                int p = p0 + pl + rr;
                int h = p >> 6, w = p & 63;
                if ((unsigned)(h + dh) >= 64u || (unsigned)(w + dw) >= 64u) {
                    uint32_t ra = sa + (pl + rr) * 32;
                    asm volatile(
                        "st.shared.v4.b32 [%0], {%1,%1,%1,%1};\n\t"
                        "st.shared.v4.b32 [%0+16], {%1,%1,%1,%1};"
                        :: "r"(ra), "r"(0u) : "memory");
                }
            }
        }
        __syncwarp();

        // B fragments: 4 ldmatrix.x4 (non-trans two-half trick)
        uint32_t bh[8][2];
        {
            uint32_t bbase = sa + 8192 + (uint32_t)(wn * 64 + (bg >> 1) * 8 + br) * 32
                           + (uint32_t)(bg & 1) * 16;
            #pragma unroll
            for (int q = 0; q < 4; q++) {
                uint32_t bq[4];
                LDSM4(bq, bbase + q * 512);     // 2 bn * 8 rows * 32B
                bh[2 * q][0]     = bq[0];
                bh[2 * q][1]     = bq[1];
                bh[2 * q + 1][0] = bq[2];
                bh[2 * q + 1][1] = bq[3];
            }
        }

        // A fragments + MMA
        uint32_t abase = sa + (uint32_t)(wm * 64 + (lane & 15)) * 32 + (uint32_t)(lane >> 4) * 16;
        #pragma unroll
        for (int am = 0; am < 4; am++) {
            uint32_t ah[4];
            LDSM4(ah, abase + am * 512);
            #pragma unroll
            for (int bn = 0; bn < 8; bn++)
                mma_f16(acc[am][bn], ah, bh[bn]);
        }

        // release slot, then producer refills
        if (lane == 0) MBAR_ARRIVE(sb + 64 + slot * 8);
        if (t == 0 && it + NSTG < 288) {
            MBAR_WAIT(sb + 64 + slot * 8, use & 1);
            issue_stage(sb, it + NSTG, n, p0, co0);
        }
    }

    __syncthreads();   // all stage traffic done; reuse smem for epilogue

    // ---- epilogue: demod * acc + noise, LeakyReLU, coalesced stores ----
    {
        float nw = nw_p[0];
        int q = lane & 3, rr = lane >> 2;
        int pxbase = p0 + wm * 64 + q * 16;
        float nzs[16];
        #pragma unroll
        for (int j = 0; j < 16; j++) nzs[j] = nw * noise[n * HW + pxbase + j];

        float* wsm = reinterpret_cast<float*>(smem + SM_DATA + wid * 2048); // 512 floats
        const float* dmrow = g_demod + n * COUT;

        #pragma unroll
        for (int g = 0; g < 8; g++) {
            #pragma unroll
            for (int am = 0; am < 4; am++) {
                int px = am * 16 + (lane >> 2);
                int col = (lane & 3) * 2;
                wsm[col * 64 + px]           = acc[am][g][0];
                wsm[(col + 1) * 64 + px]     = acc[am][g][1];
                wsm[col * 64 + px + 8]       = acc[am][g][2];
                wsm[(col + 1) * 64 + px + 8] = acc[am][g][3];
            }
            __syncwarp();
            int co = co0 + wn * 64 + g * 8 + rr;
            float d = dmrow[co];
            float* op = out + ((size_t)(n * COUT + co)) * HW + pxbase;
            const float* srp = wsm + rr * 64 + q * 16;
            #pragma unroll
            for (int j4 = 0; j4 < 4; j4++) {
                float4 v = *reinterpret_cast<const float4*>(srp + j4 * 4);
                float r0 = v.x * d + nzs[j4 * 4 + 0];
                float r1 = v.y * d + nzs[j4 * 4 + 1];
                float r2 = v.z * d + nzs[j4 * 4 + 2];
                float r3 = v.w * d + nzs[j4 * 4 + 3];
                r0 = (r0 >= 0.f) ? r0 : 0.2f * r0;
                r1 = (r1 >= 0.f) ? r1 : 0.2f * r1;
                r2 = (r2 >= 0.f) ? r2 : 0.2f * r2;
                r3 = (r3 >= 0.f) ? r3 : 0.2f * r3;
                *reinterpret_cast<float4*>(op + j4 * 4) = make_float4(r0, r1, r2, r3);
            }
            __syncwarp();
        }
    }
}

// ---------------------------------------------------------------------------
extern "C" void kernel_launch(void* const* d_in, const int* in_sizes, int n_in,
                              void* d_out, int out_size) {
    const float* x            = (const float*)d_in[0];
    const float* style        = (const float*)d_in[1];
    const float* noise        = (const float*)d_in[2];
    const float* weight       = (const float*)d_in[3];
    const float* style_w      = (const float*)d_in[4];
    const float* style_b      = (const float*)d_in[5];
    const float* noise_weight = (const float*)d_in[6];
    float* out = (float*)d_out;

    cudaFuncSetAttribute(k_main, cudaFuncAttributeMaxDynamicSharedMemorySize, SMEM_TOTAL);

    k_style<<<NB, CIN>>>(style, style_w, style_b);
    k_wsq<<<COUT, CIN>>>(weight);
    {
        dim3 g(COUT, NB);
        k_demod<<<g, 128>>>();
    }
    k_wprep<<<1024, 256>>>(weight);
    k_xmod<<<8192, 256>>>(x);
    k_main<<<1024, 256, SMEM_TOTAL>>>(noise, noise_weight, out);
}

// round 6
// speedup vs baseline: 6.9197x; 1.1036x over previous
#include <cuda_runtime.h>
#include <cuda_fp16.h>
#include <cstdint>

#define NB    16
#define CIN   512
#define COUT  512
#define STY   512
#define HW    4096
#define EPSV  1e-8f

#define XM_GUARD 2048
#define XM_ELEMS (NB * 32 * HW * 16)

// ---------------- device scratch ----------------
__device__ float g_s[NB * CIN];
__device__ float g_demod[NB * COUT];
__device__ float g_wsq[COUT * CIN];
__device__ __half g_xm[XM_ELEMS + 2 * XM_GUARD];     // x*s fp16, [n][c16][p][16]
__device__ __half g_wB[9 * 32 * COUT * 16];          // weights [tap][c16][co][16]

// ---------------- PTX helpers ----------------
__device__ __forceinline__ uint32_t smem_u32(const void* p) {
    uint32_t a;
    asm("{ .reg .u64 t; cvta.to.shared.u64 t, %1; cvt.u32.u64 %0, t; }" : "=r"(a) : "l"(p));
    return a;
}
#define MBAR_INIT(mb, c) asm volatile("mbarrier.init.shared.b64 [%0], %1;" :: "r"((uint32_t)(mb)), "r"((uint32_t)(c)) : "memory")
#define MBAR_ARRIVE(mb)  asm volatile("mbarrier.arrive.shared.b64 _, [%0];" :: "r"((uint32_t)(mb)) : "memory")
#define MBAR_EXPECT(mb, n) asm volatile("mbarrier.arrive.expect_tx.shared.b64 _, [%0], %1;" :: "r"((uint32_t)(mb)), "r"((uint32_t)(n)) : "memory")
#define FENCE_ASYNC()    asm volatile("fence.proxy.async.shared::cta;" ::: "memory")

#define MBAR_WAIT(mb, ph) do {                                                   \
    uint32_t _mb = (uint32_t)(mb); uint32_t _ph = (uint32_t)(ph); uint32_t _dn;  \
    asm volatile("{ .reg .pred p; mbarrier.try_wait.parity.acquire.cta.shared::cta.b64 p, [%1], %2; selp.b32 %0, 1, 0, p; }" \
        : "=r"(_dn) : "r"(_mb), "r"(_ph) : "memory");                            \
    if (!_dn) {                                                                  \
        asm volatile("{ .reg .pred P1;\n"                                        \
            "WL_%=: mbarrier.try_wait.parity.acquire.cta.shared::cta.b64 P1, [%0], %1, 0x989680;\n" \
            "@P1 bra.uni WD_%=;\n bra.uni WL_%=;\n WD_%=: }"                     \
            :: "r"(_mb), "r"(_ph) : "memory");                                   \
    }                                                                            \
} while (0)

#define BULK(dst, src, sz, mb) \
    asm volatile("cp.async.bulk.shared::cta.global.mbarrier::complete_tx::bytes [%0], [%1], %2, [%3];" \
        :: "r"((uint32_t)(dst)), "l"(src), "r"((uint32_t)(sz)), "r"((uint32_t)(mb)) : "memory")

#define LDSM4(r, a) \
    asm volatile("ldmatrix.sync.aligned.m8n8.x4.shared.b16 {%0,%1,%2,%3}, [%4];" \
        : "=r"((r)[0]), "=r"((r)[1]), "=r"((r)[2]), "=r"((r)[3]) : "r"(a))

__device__ __forceinline__ void mma_f16(float* c, const uint32_t* a, const uint32_t* b) {
    asm volatile("mma.sync.aligned.m16n8k16.row.col.f32.f16.f16.f32 "
        "{%0,%1,%2,%3}, {%4,%5,%6,%7}, {%8,%9}, {%0,%1,%2,%3};"
        : "+f"(c[0]), "+f"(c[1]), "+f"(c[2]), "+f"(c[3])
        : "r"(a[0]), "r"(a[1]), "r"(a[2]), "r"(a[3]), "r"(b[0]), "r"(b[1]));
}

// ---------------- prep kernels ----------------
__global__ void k_style(const float* __restrict__ style,
                        const float* __restrict__ style_w,
                        const float* __restrict__ style_b) {
    int n = blockIdx.x, ci = threadIdx.x;
    const float* srow = style + n * STY;
    const float* wrow = style_w + ci * STY;
    float acc = 0.f;
    #pragma unroll 8
    for (int j = 0; j < STY; j++) acc += srow[j] * wrow[j];
    g_s[n * CIN + ci] = acc + style_b[ci];
}

__global__ void k_wsq(const float* __restrict__ weight) {
    int co = blockIdx.x, ci = threadIdx.x;
    const float* wp = weight + (size_t)co * CIN * 9 + ci * 9;
    float s = 0.f;
    #pragma unroll
    for (int t = 0; t < 9; t++) { float v = wp[t]; s += v * v; }
    g_wsq[co * CIN + ci] = s;
}

__global__ void k_demod() {
    int co = blockIdx.x, n = blockIdx.y;
    __shared__ float red[128];
    float acc = 0.f;
    for (int ci = threadIdx.x; ci < CIN; ci += 128) {
        float s = g_s[n * CIN + ci];
        acc += g_wsq[co * CIN + ci] * s * s;
    }
    red[threadIdx.x] = acc;
    __syncthreads();
    for (int st = 64; st > 0; st >>= 1) {
        if (threadIdx.x < st) red[threadIdx.x] += red[threadIdx.x + st];
        __syncthreads();
    }
    if (threadIdx.x == 0) g_demod[n * COUT + co] = rsqrtf(red[0] + EPSV);
}

__global__ void k_wprep(const float* __restrict__ weight) {
    int id = blockIdx.x * 256 + threadIdx.x;
    int ci = id & 511, co = id >> 9;
    const float* wp = weight + (size_t)(co * CIN + ci) * 9;
    int c16 = ci >> 4, cil = ci & 15;
    #pragma unroll
    for (int tap = 0; tap < 9; tap++)
        g_wB[((size_t)(tap * 32 + c16) * COUT + co) * 16 + cil] = __float2half_rn(wp[tap]);
}

__global__ void k_xmod(const float* __restrict__ x) {
    int b   = blockIdx.x;
    int n   = b >> 9;
    int c16 = (b >> 4) & 31;
    int pb  = b & 15;
    int p   = pb * 256 + threadIdx.x;
    const float* sp = g_s + n * CIN + c16 * 16;
    const float* xp = x + (size_t)(n * CIN + c16 * 16) * HW + p;
    uint32_t hi[8];
    #pragma unroll
    for (int j = 0; j < 8; j++) {
        float v0 = xp[(size_t)(2 * j) * HW]     * sp[2 * j];
        float v1 = xp[(size_t)(2 * j + 1) * HW] * sp[2 * j + 1];
        __half2 hp = __halves2half2(__float2half_rn(v0), __float2half_rn(v1));
        hi[j] = *reinterpret_cast<uint32_t*>(&hp);
    }
    size_t ob = (size_t)XM_GUARD + ((size_t)(n * 32 + c16) * HW + p) * 16;
    uint4* oh = reinterpret_cast<uint4*>(g_xm + ob);
    oh[0] = make_uint4(hi[0], hi[1], hi[2], hi[3]);
    oh[1] = make_uint4(hi[4], hi[5], hi[6], hi[7]);
}

// ---------------- main HMMA kernel ----------------
#define NSTG      8
#define STG_BYTES 12288      // A 8192 | B 4096
#define SM_DATA   1024
#define SMEM_TOTAL (SM_DATA + NSTG * STG_BYTES)   // 99328

__device__ __forceinline__ void issue_stage(uint32_t sb, int st, int n, int p0, int co0) {
    int c16 = st / 9;
    int tap = st - c16 * 9;
    int off = (tap / 3 - 1) * 64 + (tap % 3 - 1);
    int slot = st & 7;
    uint32_t sa = sb + SM_DATA + slot * STG_BYTES;
    uint32_t mb = sb + slot * 8;
    MBAR_EXPECT(mb, STG_BYTES);
    const __half* aS = g_xm + XM_GUARD + ((long)(n * 32 + c16) * HW + p0 + off) * 16;
    const __half* bS = g_wB + ((long)(tap * 32 + c16) * COUT + co0) * 16;
    BULK(sa,        aS, 8192, mb);
    BULK(sa + 8192, bS, 4096, mb);
}

// zero-fixup of this warp's invalid A rows for stage at smem 'sa', shift (dh,dw)
__device__ __forceinline__ void fixup_rows(uint32_t sa, int p0, int wm, int lane,
                                           int dh, int dw) {
    int pl = wm * 64 + lane * 2;
    #pragma unroll
    for (int rr = 0; rr < 2; rr++) {
        int p = p0 + pl + rr;
        int h = p >> 6, w = p & 63;
        if ((unsigned)(h + dh) >= 64u || (unsigned)(w + dw) >= 64u) {
            uint32_t ra = sa + (pl + rr) * 32;
            asm volatile(
                "st.shared.v4.b32 [%0], {%1,%1,%1,%1};\n\t"
                "st.shared.v4.b32 [%0+16], {%1,%1,%1,%1};"
                :: "r"(ra), "r"(0u) : "memory");
        }
    }
    __syncwarp();
}

// B fragments for one stage into a named array (4 ldmatrix.x4)
#define LOADB(BH, sa_b, boff)                                     \
    do {                                                          \
        uint32_t _bb = (sa_b) + (boff);                           \
        uint32_t _bq[4];                                          \
        LDSM4(_bq, _bb);          (BH)[0][0]=_bq[0]; (BH)[0][1]=_bq[1]; (BH)[1][0]=_bq[2]; (BH)[1][1]=_bq[3]; \
        LDSM4(_bq, _bb + 512);    (BH)[2][0]=_bq[0]; (BH)[2][1]=_bq[1]; (BH)[3][0]=_bq[2]; (BH)[3][1]=_bq[3]; \
        LDSM4(_bq, _bb + 1024);   (BH)[4][0]=_bq[0]; (BH)[4][1]=_bq[1]; (BH)[5][0]=_bq[2]; (BH)[5][1]=_bq[3]; \
        LDSM4(_bq, _bb + 1536);   (BH)[6][0]=_bq[0]; (BH)[6][1]=_bq[1]; (BH)[7][0]=_bq[2]; (BH)[7][1]=_bq[3]; \
    } while (0)

// One pipelined iteration. CUR = B frags for 'it' (in regs), NXT gets it+1's.
#define BODY(it, CUR, NXT)                                                       \
    do {                                                                         \
        int _slot = (it) & 7;                                                    \
        uint32_t _sa = sb + SM_DATA + _slot * STG_BYTES;                         \
        /* A fragments for this iter */                                          \
        uint32_t ah0[4], ah1[4], ah2[4], ah3[4];                                 \
        LDSM4(ah0, _sa + aoff);                                                  \
        LDSM4(ah1, _sa + aoff + 512);                                            \
        LDSM4(ah2, _sa + aoff + 1024);                                           \
        LDSM4(ah3, _sa + aoff + 1536);                                           \
        if (lane == 0) MBAR_ARRIVE(sb + 64 + _slot * 8);                         \
        _Pragma("unroll")                                                        \
        for (int bn = 0; bn < 8; bn++) mma_f16(acc[0][bn], ah0, CUR[bn]);        \
        _Pragma("unroll")                                                        \
        for (int bn = 0; bn < 8; bn++) mma_f16(acc[1][bn], ah1, CUR[bn]);        \
        /* prefetch next stage's B + fixup, hidden under MMA stream */           \
        if ((it) + 1 < 288) {                                                    \
            int _ns = ((it) + 1) & 7;                                            \
            uint32_t _nsa = sb + SM_DATA + _ns * STG_BYTES;                      \
            MBAR_WAIT(sb + _ns * 8, (((it) + 1) >> 3) & 1);                      \
            fixup_rows(_nsa, p0, wm, lane, nt_dh, nt_dw);                        \
            LOADB(NXT, _nsa + 8192, boff);                                       \
        }                                                                        \
        _Pragma("unroll")                                                        \
        for (int bn = 0; bn < 8; bn++) mma_f16(acc[2][bn], ah2, CUR[bn]);        \
        _Pragma("unroll")                                                        \
        for (int bn = 0; bn < 8; bn++) mma_f16(acc[3][bn], ah3, CUR[bn]);        \
        if (t == 0 && (it) + NSTG < 288) {                                       \
            MBAR_WAIT(sb + 64 + _slot * 8, ((it) >> 3) & 1);                     \
            issue_stage(sb, (it) + NSTG, n, p0, co0);                            \
        }                                                                        \
        /* advance next-iter tap counters (track it+2's shift) */                \
        nt_dw++;                                                                 \
        if (nt_dw > 1) { nt_dw = -1; nt_dh++; if (nt_dh > 1) nt_dh = -1; }       \
    } while (0)

__global__ void __launch_bounds__(256, 1)
k_main(const float* __restrict__ noise,
       const float* __restrict__ nw_p,
       float* __restrict__ out) {
    extern __shared__ __align__(1024) char smem[];
    uint32_t sb = smem_u32(smem);
    int t = threadIdx.x, wid = t >> 5, lane = t & 31;
    int wm = wid & 3, wn = wid >> 2;

    int bx = blockIdx.x;
    int n   = bx >> 6;
    int rem = bx & 63;
    int p0  = (rem >> 2) * 256;
    int co0 = (rem & 3) * 128;

    if (t == 0) {
        #pragma unroll
        for (int s = 0; s < NSTG; s++) {
            MBAR_INIT(sb + s * 8, 1);        // full
            MBAR_INIT(sb + 64 + s * 8, 8);   // empty
        }
        FENCE_ASYNC();
    }
    __syncthreads();

    if (t == 0) {
        #pragma unroll
        for (int s = 0; s < NSTG; s++) issue_stage(sb, s, n, p0, co0);
    }

    float acc[4][8][4];
    #pragma unroll
    for (int a = 0; a < 4; a++)
        #pragma unroll
        for (int b = 0; b < 8; b++)
            #pragma unroll
            for (int c = 0; c < 4; c++) acc[a][b][c] = 0.f;

    // invariant lane offsets
    int bg = lane >> 3, br = lane & 7;
    uint32_t boff = 8192u + (uint32_t)(wn * 64 + (bg >> 1) * 8 + br) * 32
                  + (uint32_t)(bg & 1) * 16 - 8192u;          // offset within B region
    uint32_t aoff = (uint32_t)(wm * 64 + (lane & 15)) * 32 + (uint32_t)(lane >> 4) * 16;

    uint32_t bhA[8][2], bhB[8][2];

    // next-iter shift counters; prologue handles it=0 (tap 0: dh=-1,dw=-1),
    // nt_* then track the shift for stage it+1 inside BODY.
    int nt_dh = -1, nt_dw = 0;   // tap 1

    // prologue: stage 0 ready -> fixup + load B frags
    MBAR_WAIT(sb + 0, 0);
    fixup_rows(sb + SM_DATA, p0, wm, lane, -1, -1);
    LOADB(bhA, sb + SM_DATA + 8192, boff);

    for (int it2 = 0; it2 < 288; it2 += 2) {
        BODY(it2,     bhA, bhB);
        BODY(it2 + 1, bhB, bhA);
    }

    __syncthreads();   // all stage traffic done; reuse smem for epilogue

    // ---- epilogue ----
    {
        float nw = nw_p[0];
        int q = lane & 3, rr = lane >> 2;
        int pxbase = p0 + wm * 64 + q * 16;
        float nzs[16];
        #pragma unroll
        for (int j = 0; j < 16; j++) nzs[j] = nw * noise[n * HW + pxbase + j];

        float* wsm = reinterpret_cast<float*>(smem + SM_DATA + wid * 2048);
        const float* dmrow = g_demod + n * COUT;

        #pragma unroll
        for (int g = 0; g < 8; g++) {
            #pragma unroll
            for (int am = 0; am < 4; am++) {
                int px = am * 16 + (lane >> 2);
                int col = (lane & 3) * 2;
                wsm[col * 64 + px]           = acc[am][g][0];
                wsm[(col + 1) * 64 + px]     = acc[am][g][1];
                wsm[col * 64 + px + 8]       = acc[am][g][2];
                wsm[(col + 1) * 64 + px + 8] = acc[am][g][3];
            }
            __syncwarp();
            int co = co0 + wn * 64 + g * 8 + rr;
            float d = dmrow[co];
            float* op = out + ((size_t)(n * COUT + co)) * HW + pxbase;
            const float* srp = wsm + rr * 64 + q * 16;
            #pragma unroll
            for (int j4 = 0; j4 < 4; j4++) {
                float4 v = *reinterpret_cast<const float4*>(srp + j4 * 4);
                float r0 = v.x * d + nzs[j4 * 4 + 0];
                float r1 = v.y * d + nzs[j4 * 4 + 1];
                float r2 = v.z * d + nzs[j4 * 4 + 2];
                float r3 = v.w * d + nzs[j4 * 4 + 3];
                r0 = (r0 >= 0.f) ? r0 : 0.2f * r0;
                r1 = (r1 >= 0.f) ? r1 : 0.2f * r1;
                r2 = (r2 >= 0.f) ? r2 : 0.2f * r2;
                r3 = (r3 >= 0.f) ? r3 : 0.2f * r3;
                *reinterpret_cast<float4*>(op + j4 * 4) = make_float4(r0, r1, r2, r3);
            }
            __syncwarp();
        }
    }
}

// ---------------------------------------------------------------------------
extern "C" void kernel_launch(void* const* d_in, const int* in_sizes, int n_in,
                              void* d_out, int out_size) {
    const float* x            = (const float*)d_in[0];
    const float* style        = (const float*)d_in[1];
    const float* noise        = (const float*)d_in[2];
    const float* weight       = (const float*)d_in[3];
    const float* style_w      = (const float*)d_in[4];
    const float* style_b      = (const float*)d_in[5];
    const float* noise_weight = (const float*)d_in[6];
    float* out = (float*)d_out;

    cudaFuncSetAttribute(k_main, cudaFuncAttributeMaxDynamicSharedMemorySize, SMEM_TOTAL);

    k_style<<<NB, CIN>>>(style, style_w, style_b);
    k_wsq<<<COUT, CIN>>>(weight);
    {
        dim3 g(COUT, NB);
        k_demod<<<g, 128>>>();
    }
    k_wprep<<<1024, 256>>>(weight);
    k_xmod<<<8192, 256>>>(x);
    k_main<<<1024, 256, SMEM_TOTAL>>>(noise, noise_weight, out);
}

// round 7
// speedup vs baseline: 8.5668x; 1.2380x over previous
#include <cuda_runtime.h>
#include <cuda_fp16.h>
#include <cstdint>

#define NB    16
#define CIN   512
#define COUT  512
#define STY   512
#define HW    4096
#define EPSV  1e-8f

#define XM_GUARD 2048
#define XM_ELEMS (NB * 32 * HW * 16)

// ---------------- device scratch ----------------
__device__ float g_s[NB * CIN];
__device__ float g_demod[NB * COUT];
__device__ float g_wsq[COUT * CIN];
__device__ __half g_xm[XM_ELEMS + 2 * XM_GUARD];     // x*s fp16, [n][c16][p][16]
__device__ __half g_wB[9 * 32 * COUT * 16];          // weights [tap][c16][co][16]

// ---------------- PTX helpers ----------------
__device__ __forceinline__ uint32_t smem_u32(const void* p) {
    uint32_t a;
    asm("{ .reg .u64 t; cvta.to.shared.u64 t, %1; cvt.u32.u64 %0, t; }" : "=r"(a) : "l"(p));
    return a;
}
#define MBAR_INIT(mb, c) asm volatile("mbarrier.init.shared.b64 [%0], %1;" :: "r"((uint32_t)(mb)), "r"((uint32_t)(c)) : "memory")
#define MBAR_ARRIVE(mb)  asm volatile("mbarrier.arrive.shared.b64 _, [%0];" :: "r"((uint32_t)(mb)) : "memory")
#define MBAR_EXPECT(mb, n) asm volatile("mbarrier.arrive.expect_tx.shared.b64 _, [%0], %1;" :: "r"((uint32_t)(mb)), "r"((uint32_t)(n)) : "memory")
#define FENCE_ASYNC()    asm volatile("fence.proxy.async.shared::cta;" ::: "memory")

#define MBAR_WAIT(mb, ph) do {                                                   \
    uint32_t _mb = (uint32_t)(mb); uint32_t _ph = (uint32_t)(ph); uint32_t _dn;  \
    asm volatile("{ .reg .pred p; mbarrier.try_wait.parity.acquire.cta.shared::cta.b64 p, [%1], %2; selp.b32 %0, 1, 0, p; }" \
        : "=r"(_dn) : "r"(_mb), "r"(_ph) : "memory");                            \
    if (!_dn) {                                                                  \
        asm volatile("{ .reg .pred P1;\n"                                        \
            "WL_%=: mbarrier.try_wait.parity.acquire.cta.shared::cta.b64 P1, [%0], %1, 0x989680;\n" \
            "@P1 bra.uni WD_%=;\n bra.uni WL_%=;\n WD_%=: }"                     \
            :: "r"(_mb), "r"(_ph) : "memory");                                   \
    }                                                                            \
} while (0)

#define BULK(dst, src, sz, mb) \
    asm volatile("cp.async.bulk.shared::cta.global.mbarrier::complete_tx::bytes [%0], [%1], %2, [%3];" \
        :: "r"((uint32_t)(dst)), "l"(src), "r"((uint32_t)(sz)), "r"((uint32_t)(mb)) : "memory")

#define LDSM4(r, a) \
    asm volatile("ldmatrix.sync.aligned.m8n8.x4.shared.b16 {%0,%1,%2,%3}, [%4];" \
        : "=r"((r)[0]), "=r"((r)[1]), "=r"((r)[2]), "=r"((r)[3]) : "r"(a))

__device__ __forceinline__ void mma_f16(float* c, const uint32_t* a, const uint32_t* b) {
    asm volatile("mma.sync.aligned.m16n8k16.row.col.f32.f16.f16.f32 "
        "{%0,%1,%2,%3}, {%4,%5,%6,%7}, {%8,%9}, {%0,%1,%2,%3};"
        : "+f"(c[0]), "+f"(c[1]), "+f"(c[2]), "+f"(c[3])
        : "r"(a[0]), "r"(a[1]), "r"(a[2]), "r"(a[3]), "r"(b[0]), "r"(b[1]));
}

// ---------------- prep kernels ----------------
__global__ void k_style(const float* __restrict__ style,
                        const float* __restrict__ style_w,
                        const float* __restrict__ style_b) {
    int n = blockIdx.x, ci = threadIdx.x;
    const float* srow = style + n * STY;
    const float* wrow = style_w + ci * STY;
    float acc = 0.f;
    #pragma unroll 8
    for (int j = 0; j < STY; j++) acc += srow[j] * wrow[j];
    g_s[n * CIN + ci] = acc + style_b[ci];
}

// weights -> fp16 [tap][c16][co][16ci]  AND  wsq[co][ci] in one pass
__global__ void k_wprep(const float* __restrict__ weight) {
    int id = blockIdx.x * 256 + threadIdx.x;   // 262144
    int ci = id & 511, co = id >> 9;
    const float* wp = weight + (size_t)(co * CIN + ci) * 9;
    int c16 = ci >> 4, cil = ci & 15;
    float s = 0.f;
    #pragma unroll
    for (int tap = 0; tap < 9; tap++) {
        float v = wp[tap];
        s += v * v;
        g_wB[((size_t)(tap * 32 + c16) * COUT + co) * 16 + cil] = __float2half_rn(v);
    }
    g_wsq[co * CIN + ci] = s;
}

__global__ void k_demod() {
    int co = blockIdx.x, n = blockIdx.y;
    __shared__ float red[128];
    float acc = 0.f;
    for (int ci = threadIdx.x; ci < CIN; ci += 128) {
        float s = g_s[n * CIN + ci];
        acc += g_wsq[co * CIN + ci] * s * s;
    }
    red[threadIdx.x] = acc;
    __syncthreads();
    for (int st = 64; st > 0; st >>= 1) {
        if (threadIdx.x < st) red[threadIdx.x] += red[threadIdx.x + st];
        __syncthreads();
    }
    if (threadIdx.x == 0) g_demod[n * COUT + co] = rsqrtf(red[0] + EPSV);
}

__global__ void k_xmod(const float* __restrict__ x) {
    int b   = blockIdx.x;
    int n   = b >> 9;
    int c16 = (b >> 4) & 31;
    int pb  = b & 15;
    int p   = pb * 256 + threadIdx.x;
    const float* sp = g_s + n * CIN + c16 * 16;
    const float* xp = x + (size_t)(n * CIN + c16 * 16) * HW + p;
    uint32_t hi[8];
    #pragma unroll
    for (int j = 0; j < 8; j++) {
        float v0 = xp[(size_t)(2 * j) * HW]     * sp[2 * j];
        float v1 = xp[(size_t)(2 * j + 1) * HW] * sp[2 * j + 1];
        __half2 hp = __halves2half2(__float2half_rn(v0), __float2half_rn(v1));
        hi[j] = *reinterpret_cast<uint32_t*>(&hp);
    }
    size_t ob = (size_t)XM_GUARD + ((size_t)(n * 32 + c16) * HW + p) * 16;
    uint4* oh = reinterpret_cast<uint4*>(g_xm + ob);
    oh[0] = make_uint4(hi[0], hi[1], hi[2], hi[3]);
    oh[1] = make_uint4(hi[4], hi[5], hi[6], hi[7]);
}

// ---------------- main HMMA kernel ----------------
#define NSTG      8
#define STG_BYTES 12288      // A 8192 | B 4096
#define SM_DATA   1024
#define SMEM_TOTAL (SM_DATA + NSTG * STG_BYTES)   // 99328

__device__ __forceinline__ void issue_stage(uint32_t sb, int st, int n, int p0, int co0) {
    int c16 = st / 9;
    int tap = st - c16 * 9;
    int off = (tap / 3 - 1) * 64 + (tap % 3 - 1);
    int slot = st & 7;
    uint32_t sa = sb + SM_DATA + slot * STG_BYTES;
    uint32_t mb = sb + slot * 8;
    MBAR_EXPECT(mb, STG_BYTES);
    const __half* aS = g_xm + XM_GUARD + ((long)(n * 32 + c16) * HW + p0 + off) * 16;
    const __half* bS = g_wB + ((long)(tap * 32 + c16) * COUT + co0) * 16;
    BULK(sa,        aS, 8192, mb);
    BULK(sa + 8192, bS, 4096, mb);
}

__device__ __forceinline__ void fixup_rows(uint32_t sa, int p0, int wm, int lane,
                                           int dh, int dw) {
    int pl = wm * 64 + lane * 2;
    #pragma unroll
    for (int rr = 0; rr < 2; rr++) {
        int p = p0 + pl + rr;
        int h = p >> 6, w = p & 63;
        if ((unsigned)(h + dh) >= 64u || (unsigned)(w + dw) >= 64u) {
            uint32_t ra = sa + (pl + rr) * 32;
            asm volatile(
                "st.shared.v4.b32 [%0], {%1,%1,%1,%1};\n\t"
                "st.shared.v4.b32 [%0+16], {%1,%1,%1,%1};"
                :: "r"(ra), "r"(0u) : "memory");
        }
    }
    __syncwarp();
}

#define LOADB(BH, sa_b, boff)                                     \
    do {                                                          \
        uint32_t _bb = (sa_b) + (boff);                           \
        uint32_t _bq[4];                                          \
        LDSM4(_bq, _bb);          (BH)[0][0]=_bq[0]; (BH)[0][1]=_bq[1]; (BH)[1][0]=_bq[2]; (BH)[1][1]=_bq[3]; \
        LDSM4(_bq, _bb + 512);    (BH)[2][0]=_bq[0]; (BH)[2][1]=_bq[1]; (BH)[3][0]=_bq[2]; (BH)[3][1]=_bq[3]; \
        LDSM4(_bq, _bb + 1024);   (BH)[4][0]=_bq[0]; (BH)[4][1]=_bq[1]; (BH)[5][0]=_bq[2]; (BH)[5][1]=_bq[3]; \
        LDSM4(_bq, _bb + 1536);   (BH)[6][0]=_bq[0]; (BH)[6][1]=_bq[1]; (BH)[7][0]=_bq[2]; (BH)[7][1]=_bq[3]; \
    } while (0)

// One pipelined iteration. CUR = B frags for 'it' (in regs), NXT gets it+1's.
// Stage (it+NSTG) is refilled by warp (it&7) — distributed producer.
#define BODY(it, CUR, NXT)                                                       \
    do {                                                                         \
        int _slot = (it) & 7;                                                    \
        uint32_t _sa = sb + SM_DATA + _slot * STG_BYTES;                         \
        uint32_t ah0[4], ah1[4], ah2[4], ah3[4];                                 \
        LDSM4(ah0, _sa + aoff);                                                  \
        LDSM4(ah1, _sa + aoff + 512);                                            \
        LDSM4(ah2, _sa + aoff + 1024);                                           \
        LDSM4(ah3, _sa + aoff + 1536);                                           \
        if (lane == 0) MBAR_ARRIVE(sb + 64 + _slot * 8);                         \
        _Pragma("unroll")                                                        \
        for (int bn = 0; bn < 8; bn++) mma_f16(acc[0][bn], ah0, CUR[bn]);        \
        _Pragma("unroll")                                                        \
        for (int bn = 0; bn < 8; bn++) mma_f16(acc[1][bn], ah1, CUR[bn]);        \
        if ((it) + 1 < 288) {                                                    \
            int _ns = ((it) + 1) & 7;                                            \
            uint32_t _nsa = sb + SM_DATA + _ns * STG_BYTES;                      \
            MBAR_WAIT(sb + _ns * 8, (((it) + 1) >> 3) & 1);                      \
            fixup_rows(_nsa, p0, wm, lane, nt_dh, nt_dw);                        \
            LOADB(NXT, _nsa + 8192, boff);                                       \
        }                                                                        \
        _Pragma("unroll")                                                        \
        for (int bn = 0; bn < 8; bn++) mma_f16(acc[2][bn], ah2, CUR[bn]);        \
        _Pragma("unroll")                                                        \
        for (int bn = 0; bn < 8; bn++) mma_f16(acc[3][bn], ah3, CUR[bn]);        \
        if (wid == _slot && (it) + NSTG < 288) {                                 \
            if (lane == 0) {                                                     \
                MBAR_WAIT(sb + 64 + _slot * 8, ((it) >> 3) & 1);                 \
                issue_stage(sb, (it) + NSTG, n, p0, co0);                        \
            }                                                                    \
        }                                                                        \
        nt_dw++;                                                                 \
        if (nt_dw > 1) { nt_dw = -1; nt_dh++; if (nt_dh > 1) nt_dh = -1; }       \
    } while (0)

__global__ void __launch_bounds__(256, 1)
k_main(const float* __restrict__ noise,
       const float* __restrict__ nw_p,
       float* __restrict__ out) {
    extern __shared__ __align__(1024) char smem[];
    uint32_t sb = smem_u32(smem);
    int t = threadIdx.x, wid = t >> 5, lane = t & 31;
    int wm = wid & 3, wn = wid >> 2;

    int bx = blockIdx.x;
    int n   = bx >> 6;
    int rem = bx & 63;
    int p0  = (rem >> 2) * 256;
    int co0 = (rem & 3) * 128;

    if (t == 0) {
        #pragma unroll
        for (int s = 0; s < NSTG; s++) {
            MBAR_INIT(sb + s * 8, 1);        // full
            MBAR_INIT(sb + 64 + s * 8, 8);   // empty
        }
        FENCE_ASYNC();
    }
    __syncthreads();

    // parallel initial issue: warp s fills slot s
    if (lane == 0) issue_stage(sb, wid, n, p0, co0);

    float acc[4][8][4];
    #pragma unroll
    for (int a = 0; a < 4; a++)
        #pragma unroll
        for (int b = 0; b < 8; b++)
            #pragma unroll
            for (int c = 0; c < 4; c++) acc[a][b][c] = 0.f;

    // invariant lane offsets
    int bg = lane >> 3, br = lane & 7;
    uint32_t boff = (uint32_t)(wn * 64 + (bg >> 1) * 8 + br) * 32
                  + (uint32_t)(bg & 1) * 16;
    uint32_t aoff = (uint32_t)(wm * 64 + (lane & 15)) * 32 + (uint32_t)(lane >> 4) * 16;

    uint32_t bhA[8][2], bhB[8][2];
    int nt_dh = -1, nt_dw = 0;   // shift for stage it+1 (tap 1)

    // prologue: stage 0 ready -> fixup + load B frags
    MBAR_WAIT(sb + 0, 0);
    fixup_rows(sb + SM_DATA, p0, wm, lane, -1, -1);
    LOADB(bhA, sb + SM_DATA + 8192, boff);

    for (int it2 = 0; it2 < 288; it2 += 2) {
        BODY(it2,     bhA, bhB);
        BODY(it2 + 1, bhB, bhA);
    }

    __syncthreads();   // all stage traffic done; reuse smem for epilogue

    // ---- epilogue ----
    {
        float nw = nw_p[0];
        int q = lane & 3, rr = lane >> 2;
        int pxbase = p0 + wm * 64 + q * 16;
        float nzs[16];
        #pragma unroll
        for (int j = 0; j < 16; j++) nzs[j] = nw * noise[n * HW + pxbase + j];

        float* wsm = reinterpret_cast<float*>(smem + SM_DATA + wid * 2048);
        const float* dmrow = g_demod + n * COUT;

        #pragma unroll
        for (int g = 0; g < 8; g++) {
            #pragma unroll
            for (int am = 0; am < 4; am++) {
                int px = am * 16 + (lane >> 2);
                int col = (lane & 3) * 2;
                wsm[col * 64 + px]           = acc[am][g][0];
                wsm[(col + 1) * 64 + px]     = acc[am][g][1];
                wsm[col * 64 + px + 8]       = acc[am][g][2];
                wsm[(col + 1) * 64 + px + 8] = acc[am][g][3];
            }
            __syncwarp();
            int co = co0 + wn * 64 + g * 8 + rr;
            float d = dmrow[co];
            float* op = out + ((size_t)(n * COUT + co)) * HW + pxbase;
            const float* srp = wsm + rr * 64 + q * 16;
            #pragma unroll
            for (int j4 = 0; j4 < 4; j4++) {
                float4 v = *reinterpret_cast<const float4*>(srp + j4 * 4);
                float r0 = v.x * d + nzs[j4 * 4 + 0];
                float r1 = v.y * d + nzs[j4 * 4 + 1];
                float r2 = v.z * d + nzs[j4 * 4 + 2];
                float r3 = v.w * d + nzs[j4 * 4 + 3];
                r0 = (r0 >= 0.f) ? r0 : 0.2f * r0;
                r1 = (r1 >= 0.f) ? r1 : 0.2f * r1;
                r2 = (r2 >= 0.f) ? r2 : 0.2f * r2;
                r3 = (r3 >= 0.f) ? r3 : 0.2f * r3;
                *reinterpret_cast<float4*>(op + j4 * 4) = make_float4(r0, r1, r2, r3);
            }
            __syncwarp();
        }
    }
}

// ---------------------------------------------------------------------------
extern "C" void kernel_launch(void* const* d_in, const int* in_sizes, int n_in,
                              void* d_out, int out_size) {
    const float* x            = (const float*)d_in[0];
    const float* style        = (const float*)d_in[1];
    const float* noise        = (const float*)d_in[2];
    const float* weight       = (const float*)d_in[3];
    const float* style_w      = (const float*)d_in[4];
    const float* style_b      = (const float*)d_in[5];
    const float* noise_weight = (const float*)d_in[6];
    float* out = (float*)d_out;

    cudaFuncSetAttribute(k_main, cudaFuncAttributeMaxDynamicSharedMemorySize, SMEM_TOTAL);

    k_style<<<NB, CIN>>>(style, style_w, style_b);
    k_wprep<<<1024, 256>>>(weight);
    {
        dim3 g(COUT, NB);
        k_demod<<<g, 128>>>();
    }
    k_xmod<<<8192, 256>>>(x);
    k_main<<<1024, 256, SMEM_TOTAL>>>(noise, noise_weight, out);
}

// round 8
// speedup vs baseline: 9.7084x; 1.1333x over previous
#include <cuda_runtime.h>
#include <cuda_fp16.h>
#include <cstdint>

#define NB    16
#define CIN   512
#define COUT  512
#define STY   512
#define HW    4096
#define EPSV  1e-8f

#define XM_ELEMS (NB * 32 * HW * 16)

// ---------------- device scratch ----------------
__device__ float g_s[NB * CIN];
__device__ float g_demod[NB * COUT];
__device__ float g_wsq[COUT * CIN];
__device__ __align__(16) __half g_xm[XM_ELEMS];          // x*s fp16, [n][c16][p][16]
// weights fp16, [c16][cotile][tap][co128][16ci]
__device__ __align__(16) __half g_wB[32 * 4 * 9 * 128 * 16];

// ---------------- PTX helpers ----------------
__device__ __forceinline__ uint32_t smem_u32(const void* p) {
    uint32_t a;
    asm("{ .reg .u64 t; cvta.to.shared.u64 t, %1; cvt.u32.u64 %0, t; }" : "=r"(a) : "l"(p));
    return a;
}
#define MBAR_INIT(mb, c) asm volatile("mbarrier.init.shared.b64 [%0], %1;" :: "r"((uint32_t)(mb)), "r"((uint32_t)(c)) : "memory")
#define MBAR_ARRIVE(mb)  asm volatile("mbarrier.arrive.shared.b64 _, [%0];" :: "r"((uint32_t)(mb)) : "memory")
#define MBAR_EXPECT(mb, n) asm volatile("mbarrier.arrive.expect_tx.shared.b64 _, [%0], %1;" :: "r"((uint32_t)(mb)), "r"((uint32_t)(n)) : "memory")
#define FENCE_ASYNC()    asm volatile("fence.proxy.async.shared::cta;" ::: "memory")

#define MBAR_WAIT(mb, ph) do {                                                   \
    uint32_t _mb = (uint32_t)(mb); uint32_t _ph = (uint32_t)(ph); uint32_t _dn;  \
    asm volatile("{ .reg .pred p; mbarrier.try_wait.parity.acquire.cta.shared::cta.b64 p, [%1], %2; selp.b32 %0, 1, 0, p; }" \
        : "=r"(_dn) : "r"(_mb), "r"(_ph) : "memory");                            \
    if (!_dn) {                                                                  \
        asm volatile("{ .reg .pred P1;\n"                                        \
            "WL_%=: mbarrier.try_wait.parity.acquire.cta.shared::cta.b64 P1, [%0], %1, 0x989680;\n" \
            "@P1 bra.uni WD_%=;\n bra.uni WL_%=;\n WD_%=: }"                     \
            :: "r"(_mb), "r"(_ph) : "memory");                                   \
    }                                                                            \
} while (0)

#define BULK(dst, src, sz, mb) \
    asm volatile("cp.async.bulk.shared::cta.global.mbarrier::complete_tx::bytes [%0], [%1], %2, [%3];" \
        :: "r"((uint32_t)(dst)), "l"(src), "r"((uint32_t)(sz)), "r"((uint32_t)(mb)) : "memory")

#define LDSM4(r, a) \
    asm volatile("ldmatrix.sync.aligned.m8n8.x4.shared.b16 {%0,%1,%2,%3}, [%4];" \
        : "=r"((r)[0]), "=r"((r)[1]), "=r"((r)[2]), "=r"((r)[3]) : "r"(a))

__device__ __forceinline__ void mma_f16(float* c, const uint32_t* a, const uint32_t* b) {
    asm volatile("mma.sync.aligned.m16n8k16.row.col.f32.f16.f16.f32 "
        "{%0,%1,%2,%3}, {%4,%5,%6,%7}, {%8,%9}, {%0,%1,%2,%3};"
        : "+f"(c[0]), "+f"(c[1]), "+f"(c[2]), "+f"(c[3])
        : "r"(a[0]), "r"(a[1]), "r"(a[2]), "r"(a[3]), "r"(b[0]), "r"(b[1]));
}

// ---------------- prep kernels ----------------
__global__ void k_style(const float* __restrict__ style,
                        const float* __restrict__ style_w,
                        const float* __restrict__ style_b) {
    int n = blockIdx.x, ci = threadIdx.x;
    const float* srow = style + n * STY;
    const float* wrow = style_w + ci * STY;
    float acc = 0.f;
    #pragma unroll 8
    for (int j = 0; j < STY; j++) acc += srow[j] * wrow[j];
    g_s[n * CIN + ci] = acc + style_b[ci];
}

// weights -> fp16 [c16][cotile][tap][co128][16ci]  AND  wsq in one pass
__global__ void k_wprep(const float* __restrict__ weight) {
    int id = blockIdx.x * 256 + threadIdx.x;   // 262144
    int ci = id & 511, co = id >> 9;
    const float* wp = weight + (size_t)(co * CIN + ci) * 9;
    int c16 = ci >> 4, cil = ci & 15;
    int cotile = co >> 7, col = co & 127;
    float s = 0.f;
    #pragma unroll
    for (int tap = 0; tap < 9; tap++) {
        float v = wp[tap];
        s += v * v;
        g_wB[(((size_t)(c16 * 4 + cotile) * 9 + tap) * 128 + col) * 16 + cil] =
            __float2half_rn(v);
    }
    g_wsq[co * CIN + ci] = s;
}

__global__ void k_demod() {
    int co = blockIdx.x, n = blockIdx.y;
    __shared__ float red[128];
    float acc = 0.f;
    for (int ci = threadIdx.x; ci < CIN; ci += 128) {
        float s = g_s[n * CIN + ci];
        acc += g_wsq[co * CIN + ci] * s * s;
    }
    red[threadIdx.x] = acc;
    __syncthreads();
    for (int st = 64; st > 0; st >>= 1) {
        if (threadIdx.x < st) red[threadIdx.x] += red[threadIdx.x + st];
        __syncthreads();
    }
    if (threadIdx.x == 0) g_demod[n * COUT + co] = rsqrtf(red[0] + EPSV);
}

__global__ void k_xmod(const float* __restrict__ x) {
    int b   = blockIdx.x;
    int n   = b >> 9;
    int c16 = (b >> 4) & 31;
    int pb  = b & 15;
    int p   = pb * 256 + threadIdx.x;
    const float* sp = g_s + n * CIN + c16 * 16;
    const float* xp = x + (size_t)(n * CIN + c16 * 16) * HW + p;
    uint32_t hi[8];
    #pragma unroll
    for (int j = 0; j < 8; j++) {
        float v0 = xp[(size_t)(2 * j) * HW]     * sp[2 * j];
        float v1 = xp[(size_t)(2 * j + 1) * HW] * sp[2 * j + 1];
        __half2 hp = __halves2half2(__float2half_rn(v0), __float2half_rn(v1));
        hi[j] = *reinterpret_cast<uint32_t*>(&hp);
    }
    size_t ob = ((size_t)(n * 32 + c16) * HW + p) * 16;
    uint4* oh = reinterpret_cast<uint4*>(g_xm + ob);
    oh[0] = make_uint4(hi[0], hi[1], hi[2], hi[3]);
    oh[1] = make_uint4(hi[4], hi[5], hi[6], hi[7]);
}

// ---------------- main HMMA kernel ----------------
// Stage (per c16): A halo [6][66][16] halfs = 12672 B, B [9][128][16] = 36864 B
#define A_BYTES   12672
#define B_BYTES   36864
#define SSTRIDE   (A_BYTES + B_BYTES)    // 49536
#define SM_DATA   1024
#define SMEM_TOTAL (SM_DATA + 2 * SSTRIDE)   // 100096

__device__ __forceinline__ void issue_stage(uint32_t sb, int c16, int n,
                                            int h0, int cotile) {
    int slot = c16 & 1;
    uint32_t sa = sb + SM_DATA + slot * SSTRIDE;
    uint32_t mb = sb + slot * 8;
    int v = 6 - (h0 == 0) - (h0 == 60);
    MBAR_EXPECT(mb, v * 2048 + B_BYTES);
    const __half* xbase = g_xm + ((size_t)(n * 32 + c16) * HW) * 16;
    #pragma unroll
    for (int r = 0; r < 6; r++) {
        int hh = h0 - 1 + r;
        if ((unsigned)hh < 64u)
            BULK(sa + (r * 66 + 1) * 32, xbase + (size_t)hh * 64 * 16, 2048, mb);
    }
    BULK(sa + A_BYTES, g_wB + (size_t)(c16 * 4 + cotile) * 18432, B_BYTES, mb);
}

#define LOADB(BH, sa_b, boff)                                     \
    do {                                                          \
        uint32_t _bb = (sa_b) + (boff);                           \
        uint32_t _bq[4];                                          \
        LDSM4(_bq, _bb);          (BH)[0][0]=_bq[0]; (BH)[0][1]=_bq[1]; (BH)[1][0]=_bq[2]; (BH)[1][1]=_bq[3]; \
        LDSM4(_bq, _bb + 512);    (BH)[2][0]=_bq[0]; (BH)[2][1]=_bq[1]; (BH)[3][0]=_bq[2]; (BH)[3][1]=_bq[3]; \
        LDSM4(_bq, _bb + 1024);   (BH)[4][0]=_bq[0]; (BH)[4][1]=_bq[1]; (BH)[5][0]=_bq[2]; (BH)[5][1]=_bq[3]; \
        LDSM4(_bq, _bb + 1536);   (BH)[6][0]=_bq[0]; (BH)[6][1]=_bq[1]; (BH)[7][0]=_bq[2]; (BH)[7][1]=_bq[3]; \
    } while (0)

// One tap. CUR = B frags for this tap (regs); NXT receives next tap's.
// TOFF = (dh*66+dw)*32 compile-time. ISLAST = tap==8.
#define TAPB(c16v, slotv, tapv, TOFF, CUR, NXT, ISLAST)                          \
    do {                                                                         \
        uint32_t _saA = sb + SM_DATA + (slotv) * SSTRIDE;                        \
        uint32_t _aa = _saA + aoff0 + (TOFF);                                    \
        uint32_t ah0[4], ah1[4], ah2[4], ah3[4];                                 \
        LDSM4(ah0, _aa);                                                         \
        LDSM4(ah1, _aa + 512);                                                   \
        LDSM4(ah2, _aa + 1024);                                                  \
        LDSM4(ah3, _aa + 1536);                                                  \
        if (ISLAST) { if (lane == 0) MBAR_ARRIVE(sb + 64 + (slotv) * 8); }       \
        _Pragma("unroll")                                                        \
        for (int bn = 0; bn < 8; bn++) mma_f16(acc[0][bn], ah0, CUR[bn]);        \
        _Pragma("unroll")                                                        \
        for (int bn = 0; bn < 8; bn++) mma_f16(acc[1][bn], ah1, CUR[bn]);        \
        if (!(ISLAST)) {                                                         \
            LOADB(NXT, _saA + A_BYTES + ((tapv) + 1) * 4096, boff);              \
        } else if ((c16v) < 31) {                                                \
            int _ns = ((c16v) + 1) & 1;                                          \
            MBAR_WAIT(sb + _ns * 8, (((c16v) + 1) >> 1) & 1);                    \
            LOADB(NXT, sb + SM_DATA + _ns * SSTRIDE + A_BYTES, boff);            \
        }                                                                        \
        _Pragma("unroll")                                                        \
        for (int bn = 0; bn < 8; bn++) mma_f16(acc[2][bn], ah2, CUR[bn]);        \
        _Pragma("unroll")                                                        \
        for (int bn = 0; bn < 8; bn++) mma_f16(acc[3][bn], ah3, CUR[bn]);        \
        if ((ISLAST) && (c16v) + 2 < 32) {                                       \
            if (wid == ((c16v) & 7) && lane == 0) {                              \
                MBAR_WAIT(sb + 64 + (slotv) * 8, ((c16v) >> 1) & 1);             \
                issue_stage(sb, (c16v) + 2, n, h0, cotile);                      \
            }                                                                    \
        }                                                                        \
    } while (0)

// 9 taps of one stage; B0 = buffer holding tap0's frags
#define STAGE(c16v, slotv, B0, B1)                         \
    do {                                                   \
        TAPB(c16v, slotv, 0, -2144, B0, B1, 0);            \
        TAPB(c16v, slotv, 1, -2112, B1, B0, 0);            \
        TAPB(c16v, slotv, 2, -2080, B0, B1, 0);            \
        TAPB(c16v, slotv, 3,   -32, B1, B0, 0);            \
        TAPB(c16v, slotv, 4,     0, B0, B1, 0);            \
        TAPB(c16v, slotv, 5,    32, B1, B0, 0);            \
        TAPB(c16v, slotv, 6,  2080, B0, B1, 0);            \
        TAPB(c16v, slotv, 7,  2112, B1, B0, 0);            \
        TAPB(c16v, slotv, 8,  2144, B0, B1, 1);            \
    } while (0)

__global__ void __launch_bounds__(256, 1)
k_main(const float* __restrict__ noise,
       const float* __restrict__ nw_p,
       float* __restrict__ out) {
    extern __shared__ __align__(1024) char smem[];
    uint32_t sb = smem_u32(smem);
    int t = threadIdx.x, wid = t >> 5, lane = t & 31;
    int wm = wid & 3, wn = wid >> 2;

    int bx = blockIdx.x;
    int n   = bx >> 6;
    int rem = bx & 63;
    int p0  = (rem >> 2) * 256;
    int h0  = (rem >> 2) * 4;
    int co0 = (rem & 3) * 128;
    int cotile = rem & 3;

    if (t == 0) {
        #pragma unroll
        for (int s = 0; s < 2; s++) {
            MBAR_INIT(sb + s * 8, 1);        // full
            MBAR_INIT(sb + 64 + s * 8, 8);   // empty
        }
    }
    // zero both A halo regions (halo stays zero forever; interior overwritten by bulk)
    {
        uint32_t zb = sb + SM_DATA;
        for (int i = t * 16; i < A_BYTES; i += 4096) {
            asm volatile(
                "st.shared.v4.b32 [%0], {%2,%2,%2,%2};\n\t"
                "st.shared.v4.b32 [%1], {%2,%2,%2,%2};"
                :: "r"(zb + i), "r"(zb + SSTRIDE + i), "r"(0u) : "memory");
        }
    }
    __syncthreads();
    if (lane == 0 && wid < 2) {
        FENCE_ASYNC();
        issue_stage(sb, wid, n, h0, cotile);
    }

    float acc[4][8][4];
    #pragma unroll
    for (int a = 0; a < 4; a++)
        #pragma unroll
        for (int b = 0; b < 8; b++)
            #pragma unroll
            for (int c = 0; c < 4; c++) acc[a][b][c] = 0.f;

    // invariant lane offsets
    int bg = lane >> 3, br = lane & 7;
    uint32_t boff = (uint32_t)(wn * 64 + (bg >> 1) * 8 + br) * 32
                  + (uint32_t)(bg & 1) * 16;
    // A halo base (tap dh=0,dw=0): this warp's 64 px = image row h0+wm
    uint32_t aoff0 = (uint32_t)((wm + 1) * 66 + (lane & 15) + 1) * 32
                   + (uint32_t)(lane >> 4) * 16;

    uint32_t bhA[8][2], bhB[8][2];

    // prologue: stage 0 ready -> load tap0 B frags
    MBAR_WAIT(sb + 0, 0);
    LOADB(bhA, sb + SM_DATA + A_BYTES, boff);

    for (int cc = 0; cc < 32; cc += 2) {
        STAGE(cc,     0, bhA, bhB);
        STAGE(cc + 1, 1, bhB, bhA);
    }

    __syncthreads();   // all stage traffic done; reuse smem for epilogue

    // ---- epilogue: demod * acc + noise, LeakyReLU, coalesced stores ----
    {
        float nw = nw_p[0];
        int q = lane & 3, rr = lane >> 2;
        int pxbase = p0 + wm * 64 + q * 16;
        float nzs[16];
        #pragma unroll
        for (int j = 0; j < 16; j++) nzs[j] = nw * noise[n * HW + pxbase + j];

        float* wsm = reinterpret_cast<float*>(smem + SM_DATA + wid * 2048);
        const float* dmrow = g_demod + n * COUT;

        #pragma unroll
        for (int g = 0; g < 8; g++) {
            #pragma unroll
            for (int am = 0; am < 4; am++) {
                int px = am * 16 + (lane >> 2);
                int col = (lane & 3) * 2;
                wsm[col * 64 + px]           = acc[am][g][0];
                wsm[(col + 1) * 64 + px]     = acc[am][g][1];
                wsm[col * 64 + px + 8]       = acc[am][g][2];
                wsm[(col + 1) * 64 + px + 8] = acc[am][g][3];
            }
            __syncwarp();
            int co = co0 + wn * 64 + g * 8 + rr;
            float d = dmrow[co];
            float* op = out + ((size_t)(n * COUT + co)) * HW + pxbase;
            const float* srp = wsm + rr * 64 + q * 16;
            #pragma unroll
            for (int j4 = 0; j4 < 4; j4++) {
                float4 v = *reinterpret_cast<const float4*>(srp + j4 * 4);
                float r0 = v.x * d + nzs[j4 * 4 + 0];
                float r1 = v.y * d + nzs[j4 * 4 + 1];
                float r2 = v.z * d + nzs[j4 * 4 + 2];
                float r3 = v.w * d + nzs[j4 * 4 + 3];
                r0 = (r0 >= 0.f) ? r0 : 0.2f * r0;
                r1 = (r1 >= 0.f) ? r1 : 0.2f * r1;
                r2 = (r2 >= 0.f) ? r2 : 0.2f * r2;
                r3 = (r3 >= 0.f) ? r3 : 0.2f * r3;
                *reinterpret_cast<float4*>(op + j4 * 4) = make_float4(r0, r1, r2, r3);
            }
            __syncwarp();
        }
    }
}

// ---------------------------------------------------------------------------
extern "C" void kernel_launch(void* const* d_in, const int* in_sizes, int n_in,
                              void* d_out, int out_size) {
    const float* x            = (const float*)d_in[0];
    const float* style        = (const float*)d_in[1];
    const float* noise        = (const float*)d_in[2];
    const float* weight       = (const float*)d_in[3];
    const float* style_w      = (const float*)d_in[4];
    const float* style_b      = (const float*)d_in[5];
    const float* noise_weight = (const float*)d_in[6];
    float* out = (float*)d_out;

    cudaFuncSetAttribute(k_main, cudaFuncAttributeMaxDynamicSharedMemorySize, SMEM_TOTAL);

    k_style<<<NB, CIN>>>(style, style_w, style_b);
    k_wprep<<<1024, 256>>>(weight);
    {
        dim3 g(COUT, NB);
        k_demod<<<g, 128>>>();
    }
    k_xmod<<<8192, 256>>>(x);
    k_main<<<1024, 256, SMEM_TOTAL>>>(noise, noise_weight, out);
}

// round 9
// speedup vs baseline: 9.8647x; 1.0161x over previous
#include <cuda_runtime.h>
#include <cuda_fp16.h>
#include <cstdint>

#define NB    16
#define CIN   512
#define COUT  512
#define STY   512
#define HW    4096
#define EPSV  1e-8f

#define XM_ELEMS (NB * 32 * HW * 16)
#define NTILES_TOTAL 1024
#define NCTA 148

// ---------------- device scratch ----------------
__device__ float g_s[NB * CIN];
__device__ float g_demod[NB * COUT];
__device__ float g_wsq[COUT * CIN];
__device__ __align__(16) __half g_xm[XM_ELEMS];          // x*s fp16, [n][c16][p][16]
// weights fp16, [c16][cotile][tap][co128][16ci]
__device__ __align__(16) __half g_wB[32 * 4 * 9 * 128 * 16];
__device__ __align__(16) __half g_zero[1024];            // 2 KB of zeros (static init)

// ---------------- PTX helpers ----------------
__device__ __forceinline__ uint32_t smem_u32(const void* p) {
    uint32_t a;
    asm("{ .reg .u64 t; cvta.to.shared.u64 t, %1; cvt.u32.u64 %0, t; }" : "=r"(a) : "l"(p));
    return a;
}
#define MBAR_INIT(mb, c) asm volatile("mbarrier.init.shared.b64 [%0], %1;" :: "r"((uint32_t)(mb)), "r"((uint32_t)(c)) : "memory")
#define MBAR_ARRIVE(mb)  asm volatile("mbarrier.arrive.shared.b64 _, [%0];" :: "r"((uint32_t)(mb)) : "memory")
#define MBAR_EXPECT(mb, n) asm volatile("mbarrier.arrive.expect_tx.shared.b64 _, [%0], %1;" :: "r"((uint32_t)(mb)), "r"((uint32_t)(n)) : "memory")
#define FENCE_ASYNC()    asm volatile("fence.proxy.async.shared::cta;" ::: "memory")

#define MBAR_WAIT(mb, ph) do {                                                   \
    uint32_t _mb = (uint32_t)(mb); uint32_t _ph = (uint32_t)(ph); uint32_t _dn;  \
    asm volatile("{ .reg .pred p; mbarrier.try_wait.parity.acquire.cta.shared::cta.b64 p, [%1], %2; selp.b32 %0, 1, 0, p; }" \
        : "=r"(_dn) : "r"(_mb), "r"(_ph) : "memory");                            \
    if (!_dn) {                                                                  \
        asm volatile("{ .reg .pred P1;\n"                                        \
            "WL_%=: mbarrier.try_wait.parity.acquire.cta.shared::cta.b64 P1, [%0], %1, 0x989680;\n" \
            "@P1 bra.uni WD_%=;\n bra.uni WL_%=;\n WD_%=: }"                     \
            :: "r"(_mb), "r"(_ph) : "memory");                                   \
    }                                                                            \
} while (0)

#define BULK(dst, src, sz, mb) \
    asm volatile("cp.async.bulk.shared::cta.global.mbarrier::complete_tx::bytes [%0], [%1], %2, [%3];" \
        :: "r"((uint32_t)(dst)), "l"(src), "r"((uint32_t)(sz)), "r"((uint32_t)(mb)) : "memory")

#define LDSM4(r, a) \
    asm volatile("ldmatrix.sync.aligned.m8n8.x4.shared.b16 {%0,%1,%2,%3}, [%4];" \
        : "=r"((r)[0]), "=r"((r)[1]), "=r"((r)[2]), "=r"((r)[3]) : "r"(a))

__device__ __forceinline__ void mma_f16(float* c, const uint32_t* a, const uint32_t* b) {
    asm volatile("mma.sync.aligned.m16n8k16.row.col.f32.f16.f16.f32 "
        "{%0,%1,%2,%3}, {%4,%5,%6,%7}, {%8,%9}, {%0,%1,%2,%3};"
        : "+f"(c[0]), "+f"(c[1]), "+f"(c[2]), "+f"(c[3])
        : "r"(a[0]), "r"(a[1]), "r"(a[2]), "r"(a[3]), "r"(b[0]), "r"(b[1]));
}

// ---------------- prep kernels ----------------
__global__ void k_style(const float* __restrict__ style,
                        const float* __restrict__ style_w,
                        const float* __restrict__ style_b) {
    int n = blockIdx.x, ci = threadIdx.x;
    const float* srow = style + n * STY;
    const float* wrow = style_w + ci * STY;
    float acc = 0.f;
    #pragma unroll 8
    for (int j = 0; j < STY; j++) acc += srow[j] * wrow[j];
    g_s[n * CIN + ci] = acc + style_b[ci];
}

__global__ void k_wprep(const float* __restrict__ weight) {
    int id = blockIdx.x * 256 + threadIdx.x;   // 262144
    int ci = id & 511, co = id >> 9;
    const float* wp = weight + (size_t)(co * CIN + ci) * 9;
    int c16 = ci >> 4, cil = ci & 15;
    int cotile = co >> 7, col = co & 127;
    float s = 0.f;
    #pragma unroll
    for (int tap = 0; tap < 9; tap++) {
        float v = wp[tap];
        s += v * v;
        g_wB[(((size_t)(c16 * 4 + cotile) * 9 + tap) * 128 + col) * 16 + cil] =
            __float2half_rn(v);
    }
    g_wsq[co * CIN + ci] = s;
}

__global__ void k_demod() {
    int co = blockIdx.x, n = blockIdx.y;
    __shared__ float red[128];
    float acc = 0.f;
    for (int ci = threadIdx.x; ci < CIN; ci += 128) {
        float s = g_s[n * CIN + ci];
        acc += g_wsq[co * CIN + ci] * s * s;
    }
    red[threadIdx.x] = acc;
    __syncthreads();
    for (int st = 64; st > 0; st >>= 1) {
        if (threadIdx.x < st) red[threadIdx.x] += red[threadIdx.x + st];
        __syncthreads();
    }
    if (threadIdx.x == 0) g_demod[n * COUT + co] = rsqrtf(red[0] + EPSV);
}

__global__ void k_xmod(const float* __restrict__ x) {
    int b   = blockIdx.x;
    int n   = b >> 9;
    int c16 = (b >> 4) & 31;
    int pb  = b & 15;
    int p   = pb * 256 + threadIdx.x;
    const float* sp = g_s + n * CIN + c16 * 16;
    const float* xp = x + (size_t)(n * CIN + c16 * 16) * HW + p;
    uint32_t hi[8];
    #pragma unroll
    for (int j = 0; j < 8; j++) {
        float v0 = xp[(size_t)(2 * j) * HW]     * sp[2 * j];
        float v1 = xp[(size_t)(2 * j + 1) * HW] * sp[2 * j + 1];
        __half2 hp = __halves2half2(__float2half_rn(v0), __float2half_rn(v1));
        hi[j] = *reinterpret_cast<uint32_t*>(&hp);
    }
    size_t ob = ((size_t)(n * 32 + c16) * HW + p) * 16;
    uint4* oh = reinterpret_cast<uint4*>(g_xm + ob);
    oh[0] = make_uint4(hi[0], hi[1], hi[2], hi[3]);
    oh[1] = make_uint4(hi[4], hi[5], hi[6], hi[7]);
}

// ---------------- main HMMA kernel (persistent CTAs) ----------------
#define A_BYTES   12672      // [6][66][16] halfs
#define B_BYTES   36864      // [9][128][16] halfs
#define SSTRIDE   (A_BYTES + B_BYTES)    // 49536
#define SM_DATA   1024
#define SM_EPI    (SM_DATA + 2 * SSTRIDE)        // 100096
#define SMEM_TOTAL (SM_EPI + 8 * 2048)           // 116480
#define EXPECT_B  (6 * 2048 + B_BYTES)           // 49152

// issue stage with GLOBAL local-sequence index ls (tile = bx + 148*(ls>>5))
__device__ __forceinline__ void issue_stage(uint32_t sb, int ls, int bx) {
    int tord = ls >> 5, c16 = ls & 31;
    int tile = bx + NCTA * tord;
    int n = tile >> 6, rem = tile & 63;
    int h0 = (rem >> 2) * 4;
    int cotile = rem & 3;
    int slot = ls & 1;
    uint32_t sa = sb + SM_DATA + slot * SSTRIDE;
    uint32_t mb = sb + slot * 8;
    MBAR_EXPECT(mb, EXPECT_B);
    const __half* xbase = g_xm + ((size_t)(n * 32 + c16) * HW) * 16;
    #pragma unroll
    for (int r = 0; r < 6; r++) {
        int hh = h0 - 1 + r;
        const __half* src = ((unsigned)hh < 64u) ? (xbase + (size_t)hh * 64 * 16)
                                                 : g_zero;
        BULK(sa + (r * 66 + 1) * 32, src, 2048, mb);
    }
    BULK(sa + A_BYTES, g_wB + (size_t)(c16 * 4 + cotile) * 18432, B_BYTES, mb);
}

#define LOADB(BH, sa_b, boff)                                     \
    do {                                                          \
        uint32_t _bb = (sa_b) + (boff);                           \
        uint32_t _bq[4];                                          \
        LDSM4(_bq, _bb);          (BH)[0][0]=_bq[0]; (BH)[0][1]=_bq[1]; (BH)[1][0]=_bq[2]; (BH)[1][1]=_bq[3]; \
        LDSM4(_bq, _bb + 512);    (BH)[2][0]=_bq[0]; (BH)[2][1]=_bq[1]; (BH)[3][0]=_bq[2]; (BH)[3][1]=_bq[3]; \
        LDSM4(_bq, _bb + 1024);   (BH)[4][0]=_bq[0]; (BH)[4][1]=_bq[1]; (BH)[5][0]=_bq[2]; (BH)[5][1]=_bq[3]; \
        LDSM4(_bq, _bb + 1536);   (BH)[6][0]=_bq[0]; (BH)[6][1]=_bq[1]; (BH)[7][0]=_bq[2]; (BH)[7][1]=_bq[3]; \
    } while (0)

// One tap at global stage index lsv. slotv is compile-time (lsv parity).
#define TAPB(lsv, slotv, tapv, TOFF, CUR, NXT, ISLAST)                           \
    do {                                                                         \
        uint32_t _saA = sb + SM_DATA + (slotv) * SSTRIDE;                        \
        uint32_t _aa = _saA + aoff0 + (TOFF);                                    \
        uint32_t ah0[4], ah1[4], ah2[4], ah3[4];                                 \
        LDSM4(ah0, _aa);                                                         \
        LDSM4(ah1, _aa + 512);                                                   \
        LDSM4(ah2, _aa + 1024);                                                  \
        LDSM4(ah3, _aa + 1536);                                                  \
        if (ISLAST) { if (lane == 0) MBAR_ARRIVE(sb + 64 + (slotv) * 8); }       \
        _Pragma("unroll")                                                        \
        for (int bn = 0; bn < 8; bn++) mma_f16(acc[0][bn], ah0, CUR[bn]);        \
        _Pragma("unroll")                                                        \
        for (int bn = 0; bn < 8; bn++) mma_f16(acc[1][bn], ah1, CUR[bn]);        \
        if (!(ISLAST)) {                                                         \
            LOADB(NXT, _saA + A_BYTES + ((tapv) + 1) * 4096, boff);              \
        } else if ((lsv) + 1 < nls) {                                            \
            MBAR_WAIT(sb + (1 - (slotv)) * 8, (((lsv) + 1) >> 1) & 1);           \
            LOADB(NXT, sb + SM_DATA + (1 - (slotv)) * SSTRIDE + A_BYTES, boff);  \
        }                                                                        \
        _Pragma("unroll")                                                        \
        for (int bn = 0; bn < 8; bn++) mma_f16(acc[2][bn], ah2, CUR[bn]);        \
        _Pragma("unroll")                                                        \
        for (int bn = 0; bn < 8; bn++) mma_f16(acc[3][bn], ah3, CUR[bn]);        \
        if ((ISLAST) && (lsv) + 2 < nls) {                                       \
            if (wid == ((lsv) & 7) && lane == 0) {                               \
                MBAR_WAIT(sb + 64 + (slotv) * 8, ((lsv) >> 1) & 1);              \
                issue_stage(sb, (lsv) + 2, bx);                                  \
            }                                                                    \
        }                                                                        \
    } while (0)

#define STAGE(lsv, slotv, B0, B1)                          \
    do {                                                   \
        TAPB(lsv, slotv, 0, -2144, B0, B1, 0);             \
        TAPB(lsv, slotv, 1, -2112, B1, B0, 0);             \
        TAPB(lsv, slotv, 2, -2080, B0, B1, 0);             \
        TAPB(lsv, slotv, 3,   -32, B1, B0, 0);             \
        TAPB(lsv, slotv, 4,     0, B0, B1, 0);             \
        TAPB(lsv, slotv, 5,    32, B1, B0, 0);             \
        TAPB(lsv, slotv, 6,  2080, B0, B1, 0);             \
        TAPB(lsv, slotv, 7,  2112, B1, B0, 0);             \
        TAPB(lsv, slotv, 8,  2144, B0, B1, 1);             \
    } while (0)

__global__ void __launch_bounds__(256, 1)
k_main(const float* __restrict__ noise,
       const float* __restrict__ nw_p,
       float* __restrict__ out) {
    extern __shared__ __align__(1024) char smem[];
    uint32_t sb = smem_u32(smem);
    int t = threadIdx.x, wid = t >> 5, lane = t & 31;
    int wm = wid & 3, wn = wid >> 2;
    int bx = blockIdx.x;

    int ntiles = (NTILES_TOTAL - bx + NCTA - 1) / NCTA;
    int nls = ntiles * 32;

    if (t == 0) {
        #pragma unroll
        for (int s = 0; s < 2; s++) {
            MBAR_INIT(sb + s * 8, 1);        // full
            MBAR_INIT(sb + 64 + s * 8, 8);   // empty
        }
    }
    // zero both A regions (halo columns stay zero; rows always bulk-filled)
    {
        uint32_t zb = sb + SM_DATA;
        for (int i = t * 16; i < A_BYTES; i += 4096) {
            asm volatile(
                "st.shared.v4.b32 [%0], {%2,%2,%2,%2};\n\t"
                "st.shared.v4.b32 [%1], {%2,%2,%2,%2};"
                :: "r"(zb + i), "r"(zb + SSTRIDE + i), "r"(0u) : "memory");
        }
    }
    __syncthreads();
    if (lane == 0 && wid < 2) {
        FENCE_ASYNC();
        issue_stage(sb, wid, bx);
    }

    float acc[4][8][4];
    #pragma unroll
    for (int a = 0; a < 4; a++)
        #pragma unroll
        for (int b = 0; b < 8; b++)
            #pragma unroll
            for (int c = 0; c < 4; c++) acc[a][b][c] = 0.f;

    // invariant lane offsets
    int bg = lane >> 3, br = lane & 7;
    uint32_t boff = (uint32_t)(wn * 64 + (bg >> 1) * 8 + br) * 32
                  + (uint32_t)(bg & 1) * 16;
    uint32_t aoff0 = (uint32_t)((wm + 1) * 66 + (lane & 15) + 1) * 32
                   + (uint32_t)(lane >> 4) * 16;

    uint32_t bhA[8][2], bhB[8][2];
    float nw = nw_p[0];

    // prologue
    MBAR_WAIT(sb + 0, 0);
    LOADB(bhA, sb + SM_DATA + A_BYTES, boff);

    int tile = bx;
    for (int tord = 0; tord < ntiles; tord++, tile += NCTA) {
        int lsbase = tord * 32;
        for (int cc = 0; cc < 32; cc += 2) {
            STAGE(lsbase + cc,     0, bhA, bhB);
            STAGE(lsbase + cc + 1, 1, bhB, bhA);
        }

        // ---- warp-local epilogue (overlaps next tile's bulk loads) ----
        {
            int n   = tile >> 6;
            int rem = tile & 63;
            int p0  = (rem >> 2) * 256;
            int co0 = (rem & 3) * 128;

            int q = lane & 3, rr = lane >> 2;
            int pxbase = p0 + wm * 64 + q * 16;
            float nzs[16];
            #pragma unroll
            for (int j = 0; j < 16; j++) nzs[j] = nw * noise[n * HW + pxbase + j];

            float* wsm = reinterpret_cast<float*>(smem + SM_EPI + wid * 2048);
            const float* dmrow = g_demod + n * COUT;

            #pragma unroll
            for (int g = 0; g < 8; g++) {
                #pragma unroll
                for (int am = 0; am < 4; am++) {
                    int px = am * 16 + (lane >> 2);
                    int col = (lane & 3) * 2;
                    wsm[col * 64 + px]           = acc[am][g][0];
                    wsm[(col + 1) * 64 + px]     = acc[am][g][1];
                    wsm[col * 64 + px + 8]       = acc[am][g][2];
                    wsm[(col + 1) * 64 + px + 8] = acc[am][g][3];
                }
                __syncwarp();
                int co = co0 + wn * 64 + g * 8 + rr;
                float d = dmrow[co];
                float* op = out + ((size_t)(n * COUT + co)) * HW + pxbase;
                const float* srp = wsm + rr * 64 + q * 16;
                #pragma unroll
                for (int j4 = 0; j4 < 4; j4++) {
                    float4 v = *reinterpret_cast<const float4*>(srp + j4 * 4);
                    float r0 = v.x * d + nzs[j4 * 4 + 0];
                    float r1 = v.y * d + nzs[j4 * 4 + 1];
                    float r2 = v.z * d + nzs[j4 * 4 + 2];
                    float r3 = v.w * d + nzs[j4 * 4 + 3];
                    r0 = (r0 >= 0.f) ? r0 : 0.2f * r0;
                    r1 = (r1 >= 0.f) ? r1 : 0.2f * r1;
                    r2 = (r2 >= 0.f) ? r2 : 0.2f * r2;
                    r3 = (r3 >= 0.f) ? r3 : 0.2f * r3;
                    *reinterpret_cast<float4*>(op + j4 * 4) = make_float4(r0, r1, r2, r3);
                }
                __syncwarp();
            }
        }

        // reset accumulators for next tile
        #pragma unroll
        for (int a = 0; a < 4; a++)
            #pragma unroll
            for (int b = 0; b < 8; b++)
                #pragma unroll
                for (int c = 0; c < 4; c++) acc[a][b][c] = 0.f;
    }
}

// ---------------------------------------------------------------------------
extern "C" void kernel_launch(void* const* d_in, const int* in_sizes, int n_in,
                              void* d_out, int out_size) {
    const float* x            = (const float*)d_in[0];
    const float* style        = (const float*)d_in[1];
    const float* noise        = (const float*)d_in[2];
    const float* weight       = (const float*)d_in[3];
    const float* style_w      = (const float*)d_in[4];
    const float* style_b      = (const float*)d_in[5];
    const float* noise_weight = (const float*)d_in[6];
    float* out = (float*)d_out;

    cudaFuncSetAttribute(k_main, cudaFuncAttributeMaxDynamicSharedMemorySize, SMEM_TOTAL);

    k_style<<<NB, CIN>>>(style, style_w, style_b);
    k_wprep<<<1024, 256>>>(weight);
    {
        dim3 g(COUT, NB);
        k_demod<<<g, 128>>>();
    }
    k_xmod<<<8192, 256>>>(x);
    k_main<<<NCTA, 256, SMEM_TOTAL>>>(noise, noise_weight, out);
}